// round 10
// baseline (speedup 1.0000x reference)
#include <cuda_runtime.h>
#include <cuda_bf16.h>
#include <math.h>
#include <stdint.h>

#define BS   256
#define SEQ  201
#define DSSL 1024
#define D1   128
#define D2   64
#define NN   67
#define NP   53
#define NPAIR (NN*NN)      // 4489
#define NU   2278          // upper-triangle pairs (i<=j)
#define NUT  2304
#define EPSBN 1e-5f
#define MTOT  (BS*SEQ)     // 51456
#define NODES (BS*NN)      // 17152

// ---------------- scratch (device globals; no runtime allocation) ----------
__device__ float g_x [NODES * D1];
__device__ float g_x1[NODES * D1];
__device__ float g_h [NODES * D2];
__device__ float g_sc[NODES];
__device__ float g_logit[BS * NPAIR];
__device__ uint32_t g_pair[NUT];           // packed (i<<8)|j upper-tri table
__device__ float g_sc1[D1], g_of1[D1];     // folded bias+BN1 scale/offset
// pre-swizzled (SW64, 64B rows) pre-split bf16 weight images
__device__ __align__(16) unsigned char g_Bll_h[32 * 8192];
__device__ __align__(16) unsigned char g_Bll_l[32 * 8192];
__device__ __align__(16) unsigned char g_Bap_h[4 * 4096];   // k-slot-permuted
__device__ __align__(16) unsigned char g_Bap_l[4 * 4096];

// ------------------------------ helpers ------------------------------------
__device__ __forceinline__ float selu_f(float v) {
    const float a = 1.6732632423543772f, s = 1.0507009873554805f;
    return v > 0.f ? s * v : s * a * expm1f(v);
}
__device__ __forceinline__ float tanh_f(float x) {
    float e = __expf(2.0f * x);
    return 1.0f - __fdividef(2.0f, e + 1.0f);
}
__host__ __device__ __forceinline__ uint32_t sw64(uint32_t o) {
    return o ^ ((o >> 3) & 0x30);
}
__device__ __forceinline__ uint32_t smem_u32(const void* p) {
    uint32_t a;
    asm("{ .reg .u64 t; cvta.to.shared.u64 t, %1; cvt.u32.u64 %0, t; }"
        : "=r"(a) : "l"(p));
    return a;
}
__device__ __forceinline__ void split2(float v0, float v1, uint32_t& h, uint32_t& l) {
    __nv_bfloat162 hp, lp;
    hp.x = __float2bfloat16(v0);  hp.y = __float2bfloat16(v1);
    lp.x = __float2bfloat16(v0 - __bfloat162float(hp.x));
    lp.y = __float2bfloat16(v1 - __bfloat162float(hp.y));
    h = *reinterpret_cast<uint32_t*>(&hp);
    l = *reinterpret_cast<uint32_t*>(&lp);
}
__device__ __forceinline__ void mma_bf16(float* c,
    uint32_t a0, uint32_t a1, uint32_t a2, uint32_t a3,
    uint32_t b0, uint32_t b1)
{
    asm volatile(
      "mma.sync.aligned.m16n8k16.row.col.f32.bf16.bf16.f32 "
      "{%0,%1,%2,%3},{%4,%5,%6,%7},{%8,%9},{%0,%1,%2,%3};\n"
      : "+f"(c[0]), "+f"(c[1]), "+f"(c[2]), "+f"(c[3])
      : "r"(a0), "r"(a1), "r"(a2), "r"(a3), "r"(b0), "r"(b1));
}
#define LDSM4(r, a) \
    asm volatile("ldmatrix.sync.aligned.m8n8.x4.shared.b16 {%0,%1,%2,%3}, [%4];" \
        : "=r"((r)[0]), "=r"((r)[1]), "=r"((r)[2]), "=r"((r)[3]) : "r"(a))
#define CPA16(d, s) \
    asm volatile("cp.async.ca.shared.global [%0], [%1], 16;" :: "r"(d), "l"(s))
#define CPCOMMIT() asm volatile("cp.async.commit_group;" ::: "memory")
#define CPWAIT()   asm volatile("cp.async.wait_group 0;" ::: "memory")

// ========= K0: weight prep (split+swizzle), pair table, BN1 fold ===========
__global__ void k0(const float* __restrict__ Wll, const float* __restrict__ Wap,
                   const float* __restrict__ bll, const float* __restrict__ g1,
                   const float* __restrict__ b1,  const float* __restrict__ m1,
                   const float* __restrict__ v1)
{
    int idx = blockIdx.x * 256 + threadIdx.x;
    if (idx < D1 * DSSL) {
        int n = idx >> 10, k = idx & 1023;
        float v = Wll[(size_t)k * D1 + n];
        __nv_bfloat16 h = __float2bfloat16(v);
        __nv_bfloat16 l = __float2bfloat16(v - __bfloat162float(h));
        uint32_t dst = (k >> 5) * 8192 + sw64(n * 64 + (k & 31) * 2);
        *(__nv_bfloat16*)(g_Bll_h + dst) = h;
        *(__nv_bfloat16*)(g_Bll_l + dst) = l;
    } else if (idx < D1 * DSSL + D1 * D2) {
        int r = idx - D1 * DSSL;
        int k = r >> 6, c = r & 63;
        float v = Wap[(size_t)k * D2 + c];
        __nv_bfloat16 h = __float2bfloat16(v);
        __nv_bfloat16 l = __float2bfloat16(v - __bfloat162float(h));
        // k-slot permutation: orig kk (within 16) -> mma slot s so that a lane's
        // A elements are Xs[kb + 4*tg .. +3] (contiguous float4).
        int kk = k & 15;
        int s = 2 * (kk >> 2) + (kk & 1) + 8 * ((kk >> 1) & 1);
        uint32_t col = (uint32_t)(((k >> 4) & 1) * 16 + s);
        uint32_t dst = (k >> 5) * 4096 + sw64(c * 64 + col * 2);
        *(__nv_bfloat16*)(g_Bap_h + dst) = h;
        *(__nv_bfloat16*)(g_Bap_l + dst) = l;
    } else if (idx < D1 * DSSL + D1 * D2 + NUT) {
        int u = idx - (D1 * DSSL + D1 * D2);
        if (u < NU) {
            float s = sqrtf((float)((2 * NN + 1) * (2 * NN + 1) - 8 * u));
            int i = (int)(((float)(2 * NN + 1) - s) * 0.5f);
            if (i > NN - 1) i = NN - 1;
            if (i < 0) i = 0;
            while (i > 0 && i * NN - i * (i - 1) / 2 > u) i--;
            while ((i + 1) * NN - (i + 1) * i / 2 <= u) i++;
            int j = i + (u - (i * NN - i * (i - 1) / 2));
            g_pair[u] = (uint32_t)((i << 8) | j);
        } else {
            g_pair[u] = 0xFFFFFFFFu;
        }
    } else if (idx < D1 * DSSL + D1 * D2 + NUT + D1) {
        int c = idx - (D1 * DSSL + D1 * D2 + NUT);
        float sc = rsqrtf(v1[c] + EPSBN) * g1[c];
        g_sc1[c] = sc;
        g_of1[c] = (bll[c] - m1[c]) * sc + b1[c];
    }
}

// ====== K1: feat @ W_ll (hi/lo bf16 3-mma) + fused maxpool3+BN1+selu =======
// 126-row tiles (42 pool groups), BK=32 double-buffered, 16 warps.
#define K1_SMEM 67584
__global__ __launch_bounds__(512) void k1(const float* __restrict__ feat)
{
    extern __shared__ __align__(1024) unsigned char sm1[];
    uint32_t sb = smem_u32(sm1);
    const int t = threadIdx.x, lane = t & 31, wid = t >> 5;
    const int wm = wid >> 1, wn = wid & 1;
    const int m0 = blockIdx.x * 126;

    float acc[8][4];
#pragma unroll
    for (int nf = 0; nf < 8; nf++)
#pragma unroll
        for (int q = 0; q < 4; q++) acc[nf][q] = 0.f;

    const int ar = t >> 2, ak = (t & 3) * 8;
    const int arow_g = min(m0 + ar, MTOT - 1);
    const float* fp = feat + (size_t)arow_g * DSSL + ak;
    float4 fst[2];

    auto ldgA = [&](int kt) {
        const float* p = fp + kt * 32;
        fst[0] = *(const float4*)p;
        fst[1] = *(const float4*)(p + 4);
    };
    auto stsA = [&](int buf) {
        const float* vv = (const float*)fst;
        uint32_t h[4], l[4];
#pragma unroll
        for (int q = 0; q < 4; q++) split2(vv[2 * q], vv[2 * q + 1], h[q], l[q]);
        uint32_t base = (uint32_t)buf * 32768u;
        uint32_t o = sw64(ar * 64 + ak * 2);
        *(uint4*)(sm1 + base + o)        = make_uint4(h[0], h[1], h[2], h[3]);
        *(uint4*)(sm1 + base + 8192 + o) = make_uint4(l[0], l[1], l[2], l[3]);
    };
    auto cpB = [&](int kt, int buf) {
        uint32_t dh = sb + buf * 32768 + 16384 + t * 16;
        uint32_t dl = sb + buf * 32768 + 24576 + t * 16;
        CPA16(dh, g_Bll_h + kt * 8192 + t * 16);
        CPA16(dl, g_Bll_l + kt * 8192 + t * 16);
    };
    auto compute = [&](int buf) {
        uint32_t aH = sb + buf * 32768, aL = aH + 8192;
        uint32_t bH = aH + 16384, bL = aH + 24576;
#pragma unroll
        for (int kf = 0; kf < 2; kf++) {
            uint32_t ah[4], al[4];
            uint32_t off = sw64((wm * 16 + (lane & 15)) * 64 +
                                kf * 32 + (lane >> 4) * 16);
            LDSM4(ah, aH + off);
            LDSM4(al, aL + off);
#pragma unroll
            for (int nf2 = 0; nf2 < 4; nf2++) {
                uint32_t boff = sw64((wn * 64 + nf2 * 16 + (lane & 7) +
                                      ((lane >> 4) & 1) * 8) * 64 +
                                     kf * 32 + ((lane >> 3) & 1) * 16);
                uint32_t bh[4], bl[4];
                LDSM4(bh, bH + boff);
                LDSM4(bl, bL + boff);
                float* c0 = acc[nf2 * 2];
                float* c1 = acc[nf2 * 2 + 1];
                mma_bf16(c0, ah[0], ah[1], ah[2], ah[3], bh[0], bh[1]);
                mma_bf16(c0, ah[0], ah[1], ah[2], ah[3], bl[0], bl[1]);
                mma_bf16(c0, al[0], al[1], al[2], al[3], bh[0], bh[1]);
                mma_bf16(c1, ah[0], ah[1], ah[2], ah[3], bh[2], bh[3]);
                mma_bf16(c1, ah[0], ah[1], ah[2], ah[3], bl[2], bl[3]);
                mma_bf16(c1, al[0], al[1], al[2], al[3], bh[2], bh[3]);
            }
        }
    };

    ldgA(0); cpB(0, 0); CPCOMMIT();
    stsA(0);
    CPWAIT(); __syncthreads();
    for (int kt = 0; kt < 32; kt++) {
        int cur = kt & 1;
        if (kt < 31) { ldgA(kt + 1); cpB(kt + 1, cur ^ 1); CPCOMMIT(); }
        compute(cur);
        if (kt < 31) stsA(cur ^ 1);
        CPWAIT(); __syncthreads();
    }

    // ---- epilogue: stage C in smem, pool 3, folded BN1+selu -> g_x ----
    float* Cep = (float*)sm1;                       // 128 x 132
    const int g = lane >> 2, tg = lane & 3;
#pragma unroll
    for (int nf = 0; nf < 8; nf++) {
        int row = wm * 16 + g;
        int col = wn * 64 + nf * 8 + tg * 2;
        Cep[row * 132 + col]           = acc[nf][0];
        Cep[row * 132 + col + 1]       = acc[nf][1];
        Cep[(row + 8) * 132 + col]     = acc[nf][2];
        Cep[(row + 8) * 132 + col + 1] = acc[nf][3];
    }
    __syncthreads();
#pragma unroll
    for (int pass = 0; pass < 11; pass++) {
        int e = t + pass * 512;
        if (e < 42 * 128) {
            int nl = e >> 7, c = e & 127;
            const float* rp = Cep + (3 * nl) * 132 + c;
            float v = fmaxf(rp[0], fmaxf(rp[132], rp[264]));
            int node = blockIdx.x * 42 + nl;
            if (node < NODES)
                g_x[(size_t)node * D1 + c] = selu_f(v * g_sc1[c] + g_of1[c]);
        }
    }
}

// ====== K2: pair GEMM, register-built A frags, conflict-free Xs ============
// Xs stride = 128 floats (row base bank-group 0) with row-parity quad swizzle:
// quad q of row r stored at q ^ ((r&1)<<2). Consecutive rows (the 8 rows of a
// fragment group are consecutive j) land in disjoint bank-group halves ->
// LDS.128 phases are conflict-free. 68.6KB smem -> 3 CTAs/SM.
#define O2_ATT  0
#define O2_BAP  256
#define O2_PART 512
#define O2_X    1536
#define O2_WH   35840
#define O2_WL   (O2_WH + 16384)
#define K2_SMEM (O2_WL + 16384)      // 68608
__global__ __launch_bounds__(256, 3) void k2(
    const float* __restrict__ bap, const float* __restrict__ attw)
{
    extern __shared__ __align__(1024) unsigned char sm2[];
    uint32_t sb = smem_u32(sm2);
    float* attS  = (float*)(sm2 + O2_ATT);
    float* bapS  = (float*)(sm2 + O2_BAP);
    float* partS = (float*)(sm2 + O2_PART);     // [128][2]
    float* Xs    = (float*)(sm2 + O2_X);        // 67 x 128, quad-swizzled
    const int b = blockIdx.y;
    const int t = threadIdx.x, lane = t & 31;
    const int wm = t >> 6, wn = (t >> 5) & 1;
    const int g = lane >> 2, tg = lane & 3;

    {   // W hi/lo via cp.async (pre-swizzled, k-slot-permuted image)
        uint32_t dh = sb + O2_WH + t * 64, dl = sb + O2_WL + t * 64;
        const unsigned char* sh = g_Bap_h + t * 64;
        const unsigned char* sl = g_Bap_l + t * 64;
#pragma unroll
        for (int q = 0; q < 4; q++) {
            CPA16(dh + q * 16, sh + q * 16);
            CPA16(dl + q * 16, sl + q * 16);
        }
        CPCOMMIT();
    }
    if (t < 64) { attS[t] = attw[t]; bapS[t] = bap[t]; }
    {   // stage X with row-parity quad swizzle
        const float* xg = g_x + (size_t)b * NN * D1;
        for (int i = t; i < NN * 32; i += 256) {
            int row = i >> 5, q = i & 31;
            int foff = (q * 4) ^ ((row & 1) << 4);
            *(float4*)(Xs + row * 128 + foff) = *(const float4*)(xg + row * D1 + q * 4);
        }
    }
    CPWAIT(); __syncthreads();

    for (int tt = 0; tt < 3; tt++) {
        const int u0 = (blockIdx.x * 3 + tt) * 128;

        // row pair pointers + parity-XOR offsets for this lane's fragment rows
        const float *xiP[4], *xjP[4];
        int xiO[4], xjO[4];
#pragma unroll
        for (int mf = 0; mf < 2; mf++)
#pragma unroll
            for (int hh = 0; hh < 2; hh++) {
                int u = u0 + wm * 32 + mf * 16 + hh * 8 + g;
                if (u >= NU) u = NU - 1;
                uint32_t pk = g_pair[u];
                int pi = (int)(pk >> 8), pj = (int)(pk & 255);
                xiP[mf * 2 + hh] = Xs + pi * 128;
                xjP[mf * 2 + hh] = Xs + pj * 128;
                xiO[mf * 2 + hh] = (pi & 1) << 4;
                xjO[mf * 2 + hh] = (pj & 1) << 4;
            }

        float acc[2][4][4];
#pragma unroll
        for (int mf = 0; mf < 2; mf++)
#pragma unroll
            for (int nf = 0; nf < 4; nf++)
#pragma unroll
                for (int q = 0; q < 4; q++) acc[mf][nf][q] = 0.f;

#pragma unroll
        for (int c16 = 0; c16 < 8; c16++) {
            const int kb = c16 * 16 + 4 * tg;
            uint32_t bh[2][4], bl[2][4];
#pragma unroll
            for (int nf2 = 0; nf2 < 2; nf2++) {
                uint32_t boff = sw64((uint32_t)((wn * 32 + nf2 * 16 + (lane & 7) +
                                                 ((lane >> 4) & 1) * 8) * 64 +
                                                (c16 & 1) * 32 + ((lane >> 3) & 1) * 16));
                LDSM4(bh[nf2], sb + O2_WH + (c16 >> 1) * 4096 + boff);
                LDSM4(bl[nf2], sb + O2_WL + (c16 >> 1) * 4096 + boff);
            }
#pragma unroll
            for (int mf = 0; mf < 2; mf++) {
                float4 vi0 = *(const float4*)(xiP[mf * 2]     + (kb ^ xiO[mf * 2]));
                float4 vj0 = *(const float4*)(xjP[mf * 2]     + (kb ^ xjO[mf * 2]));
                float4 vi1 = *(const float4*)(xiP[mf * 2 + 1] + (kb ^ xiO[mf * 2 + 1]));
                float4 vj1 = *(const float4*)(xjP[mf * 2 + 1] + (kb ^ xjO[mf * 2 + 1]));
                uint32_t a0h, a0l, a1h, a1l, a2h, a2l, a3h, a3l;
                split2(vi0.x * vj0.x, vi0.y * vj0.y, a0h, a0l);
                split2(vi0.z * vj0.z, vi0.w * vj0.w, a2h, a2l);
                split2(vi1.x * vj1.x, vi1.y * vj1.y, a1h, a1l);
                split2(vi1.z * vj1.z, vi1.w * vj1.w, a3h, a3l);
#pragma unroll
                for (int nf2 = 0; nf2 < 2; nf2++) {
                    float* c0 = acc[mf][nf2 * 2];
                    float* c1 = acc[mf][nf2 * 2 + 1];
                    mma_bf16(c0, a0h, a1h, a2h, a3h, bh[nf2][0], bh[nf2][1]);
                    mma_bf16(c0, a0h, a1h, a2h, a3h, bl[nf2][0], bl[nf2][1]);
                    mma_bf16(c0, a0l, a1l, a2l, a3l, bh[nf2][0], bh[nf2][1]);
                    mma_bf16(c1, a0h, a1h, a2h, a3h, bh[nf2][2], bh[nf2][3]);
                    mma_bf16(c1, a0h, a1h, a2h, a3h, bl[nf2][2], bl[nf2][3]);
                    mma_bf16(c1, a0l, a1l, a2l, a3l, bh[nf2][2], bh[nf2][3]);
                }
            }
        }

        // epilogue: tanh + dot(att_w), reduce over tg, then wn halves
        float part[4] = {0.f, 0.f, 0.f, 0.f};
#pragma unroll
        for (int mf = 0; mf < 2; mf++)
#pragma unroll
            for (int nf = 0; nf < 4; nf++) {
                int col = wn * 32 + nf * 8 + tg * 2;
                float w0 = attS[col], w1 = attS[col + 1];
                float p0 = bapS[col], p1 = bapS[col + 1];
                part[mf * 2]     += w0 * tanh_f(acc[mf][nf][0] + p0) +
                                    w1 * tanh_f(acc[mf][nf][1] + p1);
                part[mf * 2 + 1] += w0 * tanh_f(acc[mf][nf][2] + p0) +
                                    w1 * tanh_f(acc[mf][nf][3] + p1);
            }
#pragma unroll
        for (int q = 0; q < 4; q++) {
            part[q] += __shfl_xor_sync(0xffffffffu, part[q], 1);
            part[q] += __shfl_xor_sync(0xffffffffu, part[q], 2);
        }
        if (tg == 0) {
#pragma unroll
            for (int mf = 0; mf < 2; mf++) {
                int r = wm * 32 + mf * 16 + g;
                partS[r * 2 + wn]       = part[mf * 2];
                partS[(r + 8) * 2 + wn] = part[mf * 2 + 1];
            }
        }
        __syncthreads();
        if (t < 128) {
            int uu = u0 + t;
            if (uu < NU) {
                uint32_t pkk = g_pair[uu];
                int i2 = (int)(pkk >> 8), j2 = (int)(pkk & 255);
                float lg = partS[t * 2] + partS[t * 2 + 1];
                g_logit[(size_t)b * NPAIR + i2 * NN + j2] = lg;
                g_logit[(size_t)b * NPAIR + j2 * NN + i2] = lg;
            }
        }
        __syncthreads();
    }
}

// ======== K2b: softmax over j per row i, then x1 = att @ X (2 rows/pass) ===
__global__ __launch_bounds__(256) void k2b()
{
    __shared__ float Xs[NN * 132];
    __shared__ float attA[8][72];
    __shared__ float attB[8][72];
    int b = blockIdx.x, t = threadIdx.x;
    int w = t >> 5, l = t & 31;

    for (int idx = t; idx < NN * D1; idx += 256)
        Xs[(idx >> 7) * 132 + (idx & 127)] = g_x[(size_t)b * NN * D1 + idx];
    __syncthreads();

    auto softmax_row = [&](int i, float* dst) {
        const float* lr = g_logit + (size_t)b * NPAIR + i * NN;
        float v0 = lr[l];
        float v1 = lr[l + 32];
        float v2 = (l + 64 < NN) ? lr[l + 64] : -1e30f;
        float mx = fmaxf(v0, fmaxf(v1, v2));
#pragma unroll
        for (int o = 16; o > 0; o >>= 1) mx = fmaxf(mx, __shfl_xor_sync(0xffffffffu, mx, o));
        float e0 = __expf(v0 - mx);
        float e1 = __expf(v1 - mx);
        float e2 = (l + 64 < NN) ? __expf(v2 - mx) : 0.f;
        float s = e0 + e1 + e2;
#pragma unroll
        for (int o = 16; o > 0; o >>= 1) s += __shfl_xor_sync(0xffffffffu, s, o);
        float inv = 1.f / s;
        dst[l] = e0 * inv;
        dst[l + 32] = e1 * inv;
        if (l + 64 < 72) dst[l + 64] = (l + 64 < NN) ? e2 * inv : 0.f;
    };

    for (int ii = w; ii < 34; ii += 8) {
        int ia = ii * 2, ib = ii * 2 + 1;
        bool hasB = (ib < NN);
        softmax_row(ia, attA[w]);
        if (hasB) {
            softmax_row(ib, attB[w]);
        } else {
            attB[w][l] = 0.f;
            attB[w][l + 32] = 0.f;
            if (l < 8) attB[w][l + 64] = 0.f;
        }
        __syncwarp();

        float4 s1 = make_float4(0.f, 0.f, 0.f, 0.f);
        float4 s2 = make_float4(0.f, 0.f, 0.f, 0.f);
        for (int j = 0; j < NN; j++) {
            float4 xv = *(const float4*)&Xs[j * 132 + l * 4];
            float a1 = attA[w][j];
            float a2 = attB[w][j];
            s1.x += a1 * xv.x; s1.y += a1 * xv.y; s1.z += a1 * xv.z; s1.w += a1 * xv.w;
            s2.x += a2 * xv.x; s2.y += a2 * xv.y; s2.z += a2 * xv.z; s2.w += a2 * xv.w;
        }
        *(float4*)&g_x1[((size_t)b * NN + ia) * D1 + l * 4] = s1;
        if (hasB)
            *(float4*)&g_x1[((size_t)b * NN + ib) * D1 + l * 4] = s2;
        __syncwarp();
    }
}

// ==== K3: h = selu(BN2(x1@W_pa + x@W_pn + biases)); score = sigmoid ========
__global__ __launch_bounds__(256) void k3(
    const float* __restrict__ Wpa, const float* __restrict__ bpa,
    const float* __restrict__ Wpn, const float* __restrict__ bpn,
    const float* __restrict__ g2, const float* __restrict__ b2,
    const float* __restrict__ m2, const float* __restrict__ v2,
    const float* __restrict__ Wpool, const float* __restrict__ bpool)
{
    __shared__ float A1[32 * 33], A2[32 * 33], Wa[32 * 64], Wb[32 * 64];
    int r0 = blockIdx.x * 32;
    int t  = threadIdx.x;
    int tm = t >> 4, tc = t & 15;
    float acc[2][4] = {};

    for (int kt = 0; kt < 4; ++kt) {
#pragma unroll
        for (int s = 0; s < 4; s++) {
            int idx = t + s * 256;
            int m = idx >> 5, k = idx & 31;
            A1[m * 33 + k] = g_x1[(size_t)(r0 + m) * D1 + kt * 32 + k];
            A2[m * 33 + k] = g_x [(size_t)(r0 + m) * D1 + kt * 32 + k];
        }
#pragma unroll
        for (int s = 0; s < 8; s++) {
            int idx = t + s * 256;
            int k = idx >> 6, c = idx & 63;
            Wa[k * 64 + c] = Wpa[(size_t)(kt * 32 + k) * D2 + c];
            Wb[k * 64 + c] = Wpn[(size_t)(kt * 32 + k) * D2 + c];
        }
        __syncthreads();
#pragma unroll 8
        for (int k = 0; k < 32; k++) {
            float4 wa = *(const float4*)&Wa[k * 64 + tc * 4];
            float4 wb = *(const float4*)&Wb[k * 64 + tc * 4];
#pragma unroll
            for (int rr = 0; rr < 2; rr++) {
                float a1 = A1[(tm * 2 + rr) * 33 + k];
                float a2 = A2[(tm * 2 + rr) * 33 + k];
                acc[rr][0] += a1 * wa.x; acc[rr][0] += a2 * wb.x;
                acc[rr][1] += a1 * wa.y; acc[rr][1] += a2 * wb.y;
                acc[rr][2] += a1 * wa.z; acc[rr][2] += a2 * wb.z;
                acc[rr][3] += a1 * wa.w; acc[rr][3] += a2 * wb.w;
            }
        }
        __syncthreads();
    }

#pragma unroll
    for (int rr = 0; rr < 2; rr++) {
        float sp = 0.f;
#pragma unroll
        for (int c = 0; c < 4; c++) {
            int cc = tc * 4 + c;
            float v = acc[rr][c] + bpa[cc] + bpn[cc];
            v = (v - m2[cc]) * rsqrtf(v2[cc] + EPSBN) * g2[cc] + b2[cc];
            v = selu_f(v);
            g_h[(size_t)(r0 + tm * 2 + rr) * D2 + cc] = v;
            sp += v * Wpool[cc];
        }
        sp += __shfl_xor_sync(0xffffffffu, sp, 8);
        sp += __shfl_xor_sync(0xffffffffu, sp, 4);
        sp += __shfl_xor_sync(0xffffffffu, sp, 2);
        sp += __shfl_xor_sync(0xffffffffu, sp, 1);
        if (tc == 0)
            g_sc[r0 + tm * 2 + rr] = 1.f / (1.f + expf(-(sp + bpool[0])));
    }
}

// ======= K4: exact stable top-k(53), gather, proj, 53x2 head ===============
__global__ __launch_bounds__(128) void k4(
    const float* __restrict__ Wproj, const float* __restrict__ bproj,
    const float* __restrict__ Wnode, const float* __restrict__ bnode,
    float* __restrict__ out)
{
    __shared__ float s[NN];
    __shared__ int   sel[NP];
    __shared__ float pv[NP];
    int b = blockIdx.x, t = threadIdx.x;

    if (t < NN) s[t] = g_sc[b * NN + t];
    __syncthreads();
    if (t < NN) {
        float st = s[t]; int rank = 0;
        for (int j = 0; j < NN; j++) {
            float sj = s[j];
            rank += (sj > st) || (sj == st && j < t);
        }
        if (rank < NP) sel[rank] = t;
    }
    __syncthreads();

    int w = t >> 5, lane = t & 31;
    for (int p = w; p < NP; p += 4) {
        int node = sel[p];
        const float* hp = g_h + ((size_t)b * NN + node) * D2;
        float d = hp[lane] * Wproj[lane] + hp[lane + 32] * Wproj[lane + 32];
#pragma unroll
        for (int o = 16; o > 0; o >>= 1) d += __shfl_xor_sync(0xffffffffu, d, o);
        if (lane == 0) pv[p] = s[node] * d + bproj[0];
    }
    __syncthreads();
    if (t < 2) {
        float o = bnode[t];
        for (int p = 0; p < NP; p++) o += pv[p] * Wnode[p * 2 + t];
        out[b * 2 + t] = o;
    }
}

// ===========================================================================
extern "C" void kernel_launch(void* const* d_in, const int* in_sizes, int n_in,
                              void* d_out, int out_size)
{
    const float* feat  = (const float*)d_in[0];
    const float* Wll   = (const float*)d_in[1];
    const float* bll   = (const float*)d_in[2];
    const float* bn1g  = (const float*)d_in[3];
    const float* bn1b  = (const float*)d_in[4];
    const float* bn1m  = (const float*)d_in[5];
    const float* bn1v  = (const float*)d_in[6];
    const float* Wap   = (const float*)d_in[7];
    const float* bap   = (const float*)d_in[8];
    const float* attw  = (const float*)d_in[9];
    const float* Wpa   = (const float*)d_in[10];
    const float* bpa   = (const float*)d_in[11];
    const float* Wpn   = (const float*)d_in[12];
    const float* bpn   = (const float*)d_in[13];
    const float* bn2g  = (const float*)d_in[14];
    const float* bn2b  = (const float*)d_in[15];
    const float* bn2m  = (const float*)d_in[16];
    const float* bn2v  = (const float*)d_in[17];
    const float* Wpool = (const float*)d_in[18];
    const float* bpool = (const float*)d_in[19];
    const float* Wproj = (const float*)d_in[20];
    const float* bproj = (const float*)d_in[21];
    const float* Wnode = (const float*)d_in[22];
    const float* bnode = (const float*)d_in[23];

    cudaFuncSetAttribute(k1, cudaFuncAttributeMaxDynamicSharedMemorySize, K1_SMEM);
    cudaFuncSetAttribute(k2, cudaFuncAttributeMaxDynamicSharedMemorySize, K2_SMEM);

    k0 <<<(D1 * DSSL + D1 * D2 + NUT + D1 + 255) / 256, 256>>>(
        Wll, Wap, bll, bn1g, bn1b, bn1m, bn1v);
    k1 <<<(MTOT + 125) / 126, 512, K1_SMEM>>>(feat);
    k2 <<<dim3(6, BS), 256, K2_SMEM>>>(bap, attw);
    k2b<<<BS, 256>>>();
    k3 <<<NODES / 32, 256>>>(Wpa, bpa, Wpn, bpn, bn2g, bn2b, bn2m, bn2v,
                             Wpool, bpool);
    k4 <<<BS, 128>>>(Wproj, bproj, Wnode, bnode, (float*)d_out);
}

// round 11
// speedup vs baseline: 1.0749x; 1.0749x over previous
#include <cuda_runtime.h>
#include <cuda_bf16.h>
#include <math.h>
#include <stdint.h>

#define BS   256
#define SEQ  201
#define DSSL 1024
#define D1   128
#define D2   64
#define NN   67
#define NP   53
#define NPAIR (NN*NN)      // 4489
#define NU   2278          // upper-triangle pairs (i<=j)
#define NUT  2304
#define EPSBN 1e-5f
#define MTOT  (BS*SEQ)     // 51456
#define NODES (BS*NN)      // 17152

// ---------------- scratch (device globals; no runtime allocation) ----------
__device__ float g_x [NODES * D1];
__device__ float g_y [NODES * D2];         // X @ W_pa
__device__ float g_z [NODES * D2];         // X @ W_pn
__device__ float g_h [NODES * D2];
__device__ float g_sc[NODES];
__device__ float g_logit[BS * NPAIR];
__device__ uint32_t g_pair[NUT];           // packed (i<<8)|j upper-tri table
__device__ float g_sc1[D1], g_of1[D1];     // folded bias+BN1 scale/offset
// pre-swizzled (SW64, 64B rows) pre-split bf16 weight images
__device__ __align__(16) unsigned char g_Bll_h[32 * 8192];
__device__ __align__(16) unsigned char g_Bll_l[32 * 8192];
__device__ __align__(16) unsigned char g_Bap_h[4 * 4096];   // k-slot-permuted
__device__ __align__(16) unsigned char g_Bap_l[4 * 4096];

// ------------------------------ helpers ------------------------------------
__device__ __forceinline__ float selu_f(float v) {
    const float a = 1.6732632423543772f, s = 1.0507009873554805f;
    return v > 0.f ? s * v : s * a * expm1f(v);
}
__device__ __forceinline__ float tanh_f(float x) {
    float e = __expf(2.0f * x);
    return 1.0f - __fdividef(2.0f, e + 1.0f);
}
__host__ __device__ __forceinline__ uint32_t sw64(uint32_t o) {
    return o ^ ((o >> 3) & 0x30);
}
__device__ __forceinline__ uint32_t smem_u32(const void* p) {
    uint32_t a;
    asm("{ .reg .u64 t; cvta.to.shared.u64 t, %1; cvt.u32.u64 %0, t; }"
        : "=r"(a) : "l"(p));
    return a;
}
__device__ __forceinline__ void split2(float v0, float v1, uint32_t& h, uint32_t& l) {
    __nv_bfloat162 hp, lp;
    hp.x = __float2bfloat16(v0);  hp.y = __float2bfloat16(v1);
    lp.x = __float2bfloat16(v0 - __bfloat162float(hp.x));
    lp.y = __float2bfloat16(v1 - __bfloat162float(hp.y));
    h = *reinterpret_cast<uint32_t*>(&hp);
    l = *reinterpret_cast<uint32_t*>(&lp);
}
__device__ __forceinline__ void mma_bf16(float* c,
    uint32_t a0, uint32_t a1, uint32_t a2, uint32_t a3,
    uint32_t b0, uint32_t b1)
{
    asm volatile(
      "mma.sync.aligned.m16n8k16.row.col.f32.bf16.bf16.f32 "
      "{%0,%1,%2,%3},{%4,%5,%6,%7},{%8,%9},{%0,%1,%2,%3};\n"
      : "+f"(c[0]), "+f"(c[1]), "+f"(c[2]), "+f"(c[3])
      : "r"(a0), "r"(a1), "r"(a2), "r"(a3), "r"(b0), "r"(b1));
}
#define LDSM4(r, a) \
    asm volatile("ldmatrix.sync.aligned.m8n8.x4.shared.b16 {%0,%1,%2,%3}, [%4];" \
        : "=r"((r)[0]), "=r"((r)[1]), "=r"((r)[2]), "=r"((r)[3]) : "r"(a))
#define CPA16(d, s) \
    asm volatile("cp.async.ca.shared.global [%0], [%1], 16;" :: "r"(d), "l"(s))
#define CPCOMMIT() asm volatile("cp.async.commit_group;" ::: "memory")
#define CPWAIT()   asm volatile("cp.async.wait_group 0;" ::: "memory")

// ========= K0: weight prep (split+swizzle), pair table, BN1 fold ===========
__global__ void k0(const float* __restrict__ Wll, const float* __restrict__ Wap,
                   const float* __restrict__ bll, const float* __restrict__ g1,
                   const float* __restrict__ b1,  const float* __restrict__ m1,
                   const float* __restrict__ v1)
{
    int idx = blockIdx.x * 256 + threadIdx.x;
    if (idx < D1 * DSSL) {
        int n = idx >> 10, k = idx & 1023;
        float v = Wll[(size_t)k * D1 + n];
        __nv_bfloat16 h = __float2bfloat16(v);
        __nv_bfloat16 l = __float2bfloat16(v - __bfloat162float(h));
        uint32_t dst = (k >> 5) * 8192 + sw64(n * 64 + (k & 31) * 2);
        *(__nv_bfloat16*)(g_Bll_h + dst) = h;
        *(__nv_bfloat16*)(g_Bll_l + dst) = l;
    } else if (idx < D1 * DSSL + D1 * D2) {
        int r = idx - D1 * DSSL;
        int k = r >> 6, c = r & 63;
        float v = Wap[(size_t)k * D2 + c];
        __nv_bfloat16 h = __float2bfloat16(v);
        __nv_bfloat16 l = __float2bfloat16(v - __bfloat162float(h));
        // k-slot permutation: orig kk (within 16) -> mma slot s so that a lane's
        // A elements are Xs[kb + 4*tg .. +3] (contiguous float4).
        int kk = k & 15;
        int s = 2 * (kk >> 2) + (kk & 1) + 8 * ((kk >> 1) & 1);
        uint32_t col = (uint32_t)(((k >> 4) & 1) * 16 + s);
        uint32_t dst = (k >> 5) * 4096 + sw64(c * 64 + col * 2);
        *(__nv_bfloat16*)(g_Bap_h + dst) = h;
        *(__nv_bfloat16*)(g_Bap_l + dst) = l;
    } else if (idx < D1 * DSSL + D1 * D2 + NUT) {
        int u = idx - (D1 * DSSL + D1 * D2);
        if (u < NU) {
            float s = sqrtf((float)((2 * NN + 1) * (2 * NN + 1) - 8 * u));
            int i = (int)(((float)(2 * NN + 1) - s) * 0.5f);
            if (i > NN - 1) i = NN - 1;
            if (i < 0) i = 0;
            while (i > 0 && i * NN - i * (i - 1) / 2 > u) i--;
            while ((i + 1) * NN - (i + 1) * i / 2 <= u) i++;
            int j = i + (u - (i * NN - i * (i - 1) / 2));
            g_pair[u] = (uint32_t)((i << 8) | j);
        } else {
            g_pair[u] = 0xFFFFFFFFu;
        }
    } else if (idx < D1 * DSSL + D1 * D2 + NUT + D1) {
        int c = idx - (D1 * DSSL + D1 * D2 + NUT);
        float sc = rsqrtf(v1[c] + EPSBN) * g1[c];
        g_sc1[c] = sc;
        g_of1[c] = (bll[c] - m1[c]) * sc + b1[c];
    }
}

// ====== K1: feat @ W_ll (hi/lo bf16 3-mma) + fused maxpool3+BN1+selu =======
// 126-row tiles (42 pool groups), BK=32 double-buffered, 16 warps.
#define K1_SMEM 67584
__global__ __launch_bounds__(512) void k1(const float* __restrict__ feat)
{
    extern __shared__ __align__(1024) unsigned char sm1[];
    uint32_t sb = smem_u32(sm1);
    const int t = threadIdx.x, lane = t & 31, wid = t >> 5;
    const int wm = wid >> 1, wn = wid & 1;
    const int m0 = blockIdx.x * 126;

    float acc[8][4];
#pragma unroll
    for (int nf = 0; nf < 8; nf++)
#pragma unroll
        for (int q = 0; q < 4; q++) acc[nf][q] = 0.f;

    const int ar = t >> 2, ak = (t & 3) * 8;
    const int arow_g = min(m0 + ar, MTOT - 1);
    const float* fp = feat + (size_t)arow_g * DSSL + ak;
    float4 fst[2];

    auto ldgA = [&](int kt) {
        const float* p = fp + kt * 32;
        fst[0] = *(const float4*)p;
        fst[1] = *(const float4*)(p + 4);
    };
    auto stsA = [&](int buf) {
        const float* vv = (const float*)fst;
        uint32_t h[4], l[4];
#pragma unroll
        for (int q = 0; q < 4; q++) split2(vv[2 * q], vv[2 * q + 1], h[q], l[q]);
        uint32_t base = (uint32_t)buf * 32768u;
        uint32_t o = sw64(ar * 64 + ak * 2);
        *(uint4*)(sm1 + base + o)        = make_uint4(h[0], h[1], h[2], h[3]);
        *(uint4*)(sm1 + base + 8192 + o) = make_uint4(l[0], l[1], l[2], l[3]);
    };
    auto cpB = [&](int kt, int buf) {
        uint32_t dh = sb + buf * 32768 + 16384 + t * 16;
        uint32_t dl = sb + buf * 32768 + 24576 + t * 16;
        CPA16(dh, g_Bll_h + kt * 8192 + t * 16);
        CPA16(dl, g_Bll_l + kt * 8192 + t * 16);
    };
    auto compute = [&](int buf) {
        uint32_t aH = sb + buf * 32768, aL = aH + 8192;
        uint32_t bH = aH + 16384, bL = aH + 24576;
#pragma unroll
        for (int kf = 0; kf < 2; kf++) {
            uint32_t ah[4], al[4];
            uint32_t off = sw64((wm * 16 + (lane & 15)) * 64 +
                                kf * 32 + (lane >> 4) * 16);
            LDSM4(ah, aH + off);
            LDSM4(al, aL + off);
#pragma unroll
            for (int nf2 = 0; nf2 < 4; nf2++) {
                uint32_t boff = sw64((wn * 64 + nf2 * 16 + (lane & 7) +
                                      ((lane >> 4) & 1) * 8) * 64 +
                                     kf * 32 + ((lane >> 3) & 1) * 16);
                uint32_t bh[4], bl[4];
                LDSM4(bh, bH + boff);
                LDSM4(bl, bL + boff);
                float* c0 = acc[nf2 * 2];
                float* c1 = acc[nf2 * 2 + 1];
                mma_bf16(c0, ah[0], ah[1], ah[2], ah[3], bh[0], bh[1]);
                mma_bf16(c0, ah[0], ah[1], ah[2], ah[3], bl[0], bl[1]);
                mma_bf16(c0, al[0], al[1], al[2], al[3], bh[0], bh[1]);
                mma_bf16(c1, ah[0], ah[1], ah[2], ah[3], bh[2], bh[3]);
                mma_bf16(c1, ah[0], ah[1], ah[2], ah[3], bl[2], bl[3]);
                mma_bf16(c1, al[0], al[1], al[2], al[3], bh[2], bh[3]);
            }
        }
    };

    ldgA(0); cpB(0, 0); CPCOMMIT();
    stsA(0);
    CPWAIT(); __syncthreads();
    for (int kt = 0; kt < 32; kt++) {
        int cur = kt & 1;
        if (kt < 31) { ldgA(kt + 1); cpB(kt + 1, cur ^ 1); CPCOMMIT(); }
        compute(cur);
        if (kt < 31) stsA(cur ^ 1);
        CPWAIT(); __syncthreads();
    }

    // ---- epilogue: stage C in smem, pool 3, folded BN1+selu -> g_x ----
    float* Cep = (float*)sm1;                       // 128 x 132
    const int g = lane >> 2, tg = lane & 3;
#pragma unroll
    for (int nf = 0; nf < 8; nf++) {
        int row = wm * 16 + g;
        int col = wn * 64 + nf * 8 + tg * 2;
        Cep[row * 132 + col]           = acc[nf][0];
        Cep[row * 132 + col + 1]       = acc[nf][1];
        Cep[(row + 8) * 132 + col]     = acc[nf][2];
        Cep[(row + 8) * 132 + col + 1] = acc[nf][3];
    }
    __syncthreads();
#pragma unroll
    for (int pass = 0; pass < 11; pass++) {
        int e = t + pass * 512;
        if (e < 42 * 128) {
            int nl = e >> 7, c = e & 127;
            const float* rp = Cep + (3 * nl) * 132 + c;
            float v = fmaxf(rp[0], fmaxf(rp[132], rp[264]));
            int node = blockIdx.x * 42 + nl;
            if (node < NODES)
                g_x[(size_t)node * D1 + c] = selu_f(v * g_sc1[c] + g_of1[c]);
        }
    }
}

// ====== K2: pair GEMM with register-built A fragments (sync-free loop) =====
// (R9 structure — the measured-best variant)
#define O2_ATT  0
#define O2_BAP  256
#define O2_PART 512
#define O2_X    1536
#define O2_WH   37888
#define O2_WL   (O2_WH + 16384)
#define K2_SMEM (O2_WL + 16384)      // 70656
__global__ __launch_bounds__(256, 2) void k2(
    const float* __restrict__ bap, const float* __restrict__ attw)
{
    extern __shared__ __align__(1024) unsigned char sm2[];
    uint32_t sb = smem_u32(sm2);
    float* attS  = (float*)(sm2 + O2_ATT);
    float* bapS  = (float*)(sm2 + O2_BAP);
    float* partS = (float*)(sm2 + O2_PART);     // [128][2]
    float* Xs    = (float*)(sm2 + O2_X);        // 67 x 132
    const int b = blockIdx.y;
    const int t = threadIdx.x, lane = t & 31;
    const int wm = t >> 6, wn = (t >> 5) & 1;
    const int g = lane >> 2, tg = lane & 3;

    {   // W hi/lo via cp.async (pre-swizzled, k-slot-permuted image)
        uint32_t dh = sb + O2_WH + t * 64, dl = sb + O2_WL + t * 64;
        const unsigned char* sh = g_Bap_h + t * 64;
        const unsigned char* sl = g_Bap_l + t * 64;
#pragma unroll
        for (int q = 0; q < 4; q++) {
            CPA16(dh + q * 16, sh + q * 16);
            CPA16(dl + q * 16, sl + q * 16);
        }
        CPCOMMIT();
    }
    if (t < 64) { attS[t] = attw[t]; bapS[t] = bap[t]; }
    {   // stage X
        const float* xg = g_x + (size_t)b * NN * D1;
        for (int i = t; i < NN * 32; i += 256) {
            int row = i >> 5, c4 = (i & 31) * 4;
            *(float4*)(Xs + row * 132 + c4) = *(const float4*)(xg + row * D1 + c4);
        }
    }
    CPWAIT(); __syncthreads();

    for (int tt = 0; tt < 3; tt++) {
        const int u0 = (blockIdx.x * 3 + tt) * 128;

        // row pair pointers for this lane's 4 fragment rows
        const float *xiP[4], *xjP[4];
#pragma unroll
        for (int mf = 0; mf < 2; mf++)
#pragma unroll
            for (int hh = 0; hh < 2; hh++) {
                int u = u0 + wm * 32 + mf * 16 + hh * 8 + g;
                if (u >= NU) u = NU - 1;
                uint32_t pk = g_pair[u];
                xiP[mf * 2 + hh] = Xs + (pk >> 8) * 132;
                xjP[mf * 2 + hh] = Xs + (pk & 255) * 132;
            }

        float acc[2][4][4];
#pragma unroll
        for (int mf = 0; mf < 2; mf++)
#pragma unroll
            for (int nf = 0; nf < 4; nf++)
#pragma unroll
                for (int q = 0; q < 4; q++) acc[mf][nf][q] = 0.f;

#pragma unroll
        for (int c16 = 0; c16 < 8; c16++) {
            const int kb = c16 * 16 + 4 * tg;
            uint32_t bh[2][4], bl[2][4];
#pragma unroll
            for (int nf2 = 0; nf2 < 2; nf2++) {
                uint32_t boff = sw64((uint32_t)((wn * 32 + nf2 * 16 + (lane & 7) +
                                                 ((lane >> 4) & 1) * 8) * 64 +
                                                (c16 & 1) * 32 + ((lane >> 3) & 1) * 16));
                LDSM4(bh[nf2], sb + O2_WH + (c16 >> 1) * 4096 + boff);
                LDSM4(bl[nf2], sb + O2_WL + (c16 >> 1) * 4096 + boff);
            }
#pragma unroll
            for (int mf = 0; mf < 2; mf++) {
                float4 vi0 = *(const float4*)(xiP[mf * 2] + kb);
                float4 vj0 = *(const float4*)(xjP[mf * 2] + kb);
                float4 vi1 = *(const float4*)(xiP[mf * 2 + 1] + kb);
                float4 vj1 = *(const float4*)(xjP[mf * 2 + 1] + kb);
                uint32_t a0h, a0l, a1h, a1l, a2h, a2l, a3h, a3l;
                split2(vi0.x * vj0.x, vi0.y * vj0.y, a0h, a0l);
                split2(vi0.z * vj0.z, vi0.w * vj0.w, a2h, a2l);
                split2(vi1.x * vj1.x, vi1.y * vj1.y, a1h, a1l);
                split2(vi1.z * vj1.z, vi1.w * vj1.w, a3h, a3l);
#pragma unroll
                for (int nf2 = 0; nf2 < 2; nf2++) {
                    float* c0 = acc[mf][nf2 * 2];
                    float* c1 = acc[mf][nf2 * 2 + 1];
                    mma_bf16(c0, a0h, a1h, a2h, a3h, bh[nf2][0], bh[nf2][1]);
                    mma_bf16(c0, a0h, a1h, a2h, a3h, bl[nf2][0], bl[nf2][1]);
                    mma_bf16(c0, a0l, a1l, a2l, a3l, bh[nf2][0], bh[nf2][1]);
                    mma_bf16(c1, a0h, a1h, a2h, a3h, bh[nf2][2], bh[nf2][3]);
                    mma_bf16(c1, a0h, a1h, a2h, a3h, bl[nf2][2], bl[nf2][3]);
                    mma_bf16(c1, a0l, a1l, a2l, a3l, bh[nf2][2], bh[nf2][3]);
                }
            }
        }

        // epilogue: tanh + dot(att_w), reduce over tg, then wn halves
        float part[4] = {0.f, 0.f, 0.f, 0.f};
#pragma unroll
        for (int mf = 0; mf < 2; mf++)
#pragma unroll
            for (int nf = 0; nf < 4; nf++) {
                int col = wn * 32 + nf * 8 + tg * 2;
                float w0 = attS[col], w1 = attS[col + 1];
                float p0 = bapS[col], p1 = bapS[col + 1];
                part[mf * 2]     += w0 * tanh_f(acc[mf][nf][0] + p0) +
                                    w1 * tanh_f(acc[mf][nf][1] + p1);
                part[mf * 2 + 1] += w0 * tanh_f(acc[mf][nf][2] + p0) +
                                    w1 * tanh_f(acc[mf][nf][3] + p1);
            }
#pragma unroll
        for (int q = 0; q < 4; q++) {
            part[q] += __shfl_xor_sync(0xffffffffu, part[q], 1);
            part[q] += __shfl_xor_sync(0xffffffffu, part[q], 2);
        }
        if (tg == 0) {
#pragma unroll
            for (int mf = 0; mf < 2; mf++) {
                int r = wm * 32 + mf * 16 + g;
                partS[r * 2 + wn]       = part[mf * 2];
                partS[(r + 8) * 2 + wn] = part[mf * 2 + 1];
            }
        }
        __syncthreads();
        if (t < 128) {
            int uu = u0 + t;
            if (uu < NU) {
                uint32_t pkk = g_pair[uu];
                int i2 = (int)(pkk >> 8), j2 = (int)(pkk & 255);
                float lg = partS[t * 2] + partS[t * 2 + 1];
                g_logit[(size_t)b * NPAIR + i2 * NN + j2] = lg;
                g_logit[(size_t)b * NPAIR + j2 * NN + i2] = lg;
            }
        }
        __syncthreads();
    }
}

// ==== KY: Y = x@W_pa, Z = x@W_pn  (raw, no BN) =============================
__global__ __launch_bounds__(256) void ky(
    const float* __restrict__ Wpa, const float* __restrict__ Wpn)
{
    __shared__ float A[32 * 33], Wa[32 * 64], Wb[32 * 64];
    int r0 = blockIdx.x * 32;
    int t  = threadIdx.x;
    int tm = t >> 4, tc = t & 15;
    float accA[2][4] = {}, accB[2][4] = {};

    for (int kt = 0; kt < 4; ++kt) {
#pragma unroll
        for (int s = 0; s < 4; s++) {
            int idx = t + s * 256;
            int m = idx >> 5, k = idx & 31;
            A[m * 33 + k] = g_x[(size_t)(r0 + m) * D1 + kt * 32 + k];
        }
#pragma unroll
        for (int s = 0; s < 8; s++) {
            int idx = t + s * 256;
            int k = idx >> 6, c = idx & 63;
            Wa[k * 64 + c] = Wpa[(size_t)(kt * 32 + k) * D2 + c];
            Wb[k * 64 + c] = Wpn[(size_t)(kt * 32 + k) * D2 + c];
        }
        __syncthreads();
#pragma unroll 8
        for (int k = 0; k < 32; k++) {
            float4 wa = *(const float4*)&Wa[k * 64 + tc * 4];
            float4 wb = *(const float4*)&Wb[k * 64 + tc * 4];
#pragma unroll
            for (int rr = 0; rr < 2; rr++) {
                float a = A[(tm * 2 + rr) * 33 + k];
                accA[rr][0] += a * wa.x;  accB[rr][0] += a * wb.x;
                accA[rr][1] += a * wa.y;  accB[rr][1] += a * wb.y;
                accA[rr][2] += a * wa.z;  accB[rr][2] += a * wb.z;
                accA[rr][3] += a * wa.w;  accB[rr][3] += a * wb.w;
            }
        }
        __syncthreads();
    }

#pragma unroll
    for (int rr = 0; rr < 2; rr++) {
        size_t base = (size_t)(r0 + tm * 2 + rr) * D2 + tc * 4;
        *(float4*)&g_y[base] = make_float4(accA[rr][0], accA[rr][1],
                                           accA[rr][2], accA[rr][3]);
        *(float4*)&g_z[base] = make_float4(accB[rr][0], accB[rr][1],
                                           accB[rr][2], accB[rr][3]);
    }
}

// ==== K2C: softmax + h = selu(BN2(att@Y + Z + biases)) + score =============
__global__ __launch_bounds__(256) void k2c(
    const float* __restrict__ bpa, const float* __restrict__ bpn,
    const float* __restrict__ g2, const float* __restrict__ b2,
    const float* __restrict__ m2, const float* __restrict__ v2,
    const float* __restrict__ Wpool, const float* __restrict__ bpool)
{
    __shared__ float Ys[NN * 68];      // Y staged, stride 68 (16B-aligned rows)
    __shared__ float attS[8][68];
    int b = blockIdx.x, t = threadIdx.x;
    int w = t >> 5, l = t & 31;

    for (int i = t; i < NN * 16; i += 256) {
        int row = i >> 4, q = i & 15;
        *(float4*)(Ys + row * 68 + q * 4) =
            *(const float4*)(g_y + ((size_t)b * NN + row) * D2 + q * 4);
    }
    __syncthreads();

    // per-lane BN2/bias constants for cols c0 = l, c1 = l+32
    const int c0 = l, c1 = l + 32;
    const float bb0 = bpa[c0] + bpn[c0], bb1 = bpa[c1] + bpn[c1];
    const float s0 = rsqrtf(v2[c0] + EPSBN) * g2[c0];
    const float s1 = rsqrtf(v2[c1] + EPSBN) * g2[c1];
    const float m0 = m2[c0], m1v = m2[c1];
    const float o0 = b2[c0], o1 = b2[c1];
    const float wp0 = Wpool[c0], wp1 = Wpool[c1];
    const float bp = bpool[0];

    for (int i = w; i < NN; i += 8) {
        // ---- softmax over j of logit row i ----
        const float* lr = g_logit + (size_t)b * NPAIR + i * NN;
        float v0 = lr[l];
        float v1 = lr[l + 32];
        float vv2 = (l < 3) ? lr[l + 64] : -1e30f;
        float mx = fmaxf(v0, fmaxf(v1, vv2));
#pragma unroll
        for (int o = 16; o > 0; o >>= 1) mx = fmaxf(mx, __shfl_xor_sync(0xffffffffu, mx, o));
        float e0 = __expf(v0 - mx);
        float e1 = __expf(v1 - mx);
        float e2 = (l < 3) ? __expf(vv2 - mx) : 0.f;
        float ss = e0 + e1 + e2;
#pragma unroll
        for (int o = 16; o > 0; o >>= 1) ss += __shfl_xor_sync(0xffffffffu, ss, o);
        float inv = 1.f / ss;
        attS[w][l] = e0 * inv;
        attS[w][l + 32] = e1 * inv;
        if (l < 3) attS[w][l + 64] = e2 * inv;
        __syncwarp();

        // ---- att @ Y: cols c0, c1 ----
        float a0 = 0.f, a1 = 0.f;
        for (int j = 0; j < NN; j++) {
            float a = attS[w][j];
            a0 += a * Ys[j * 68 + c0];
            a1 += a * Ys[j * 68 + c1];
        }
        size_t zb = ((size_t)b * NN + i) * D2;
        float u0 = a0 + g_z[zb + c0] + bb0;
        float u1 = a1 + g_z[zb + c1] + bb1;
        u0 = selu_f((u0 - m0) * s0 + o0);
        u1 = selu_f((u1 - m1v) * s1 + o1);
        g_h[zb + c0] = u0;
        g_h[zb + c1] = u1;
        float sp = u0 * wp0 + u1 * wp1;
#pragma unroll
        for (int o = 16; o > 0; o >>= 1) sp += __shfl_xor_sync(0xffffffffu, sp, o);
        if (l == 0) g_sc[b * NN + i] = 1.f / (1.f + expf(-(sp + bp)));
        __syncwarp();
    }
}

// ======= K4: exact stable top-k(53), gather, proj, 53x2 head ===============
__global__ __launch_bounds__(128) void k4(
    const float* __restrict__ Wproj, const float* __restrict__ bproj,
    const float* __restrict__ Wnode, const float* __restrict__ bnode,
    float* __restrict__ out)
{
    __shared__ float s[NN];
    __shared__ int   sel[NP];
    __shared__ float pv[NP];
    int b = blockIdx.x, t = threadIdx.x;

    if (t < NN) s[t] = g_sc[b * NN + t];
    __syncthreads();
    if (t < NN) {
        float st = s[t]; int rank = 0;
        for (int j = 0; j < NN; j++) {
            float sj = s[j];
            rank += (sj > st) || (sj == st && j < t);
        }
        if (rank < NP) sel[rank] = t;
    }
    __syncthreads();

    int w = t >> 5, lane = t & 31;
    for (int p = w; p < NP; p += 4) {
        int node = sel[p];
        const float* hp = g_h + ((size_t)b * NN + node) * D2;
        float d = hp[lane] * Wproj[lane] + hp[lane + 32] * Wproj[lane + 32];
#pragma unroll
        for (int o = 16; o > 0; o >>= 1) d += __shfl_xor_sync(0xffffffffu, d, o);
        if (lane == 0) pv[p] = s[node] * d + bproj[0];
    }
    __syncthreads();
    if (t < 2) {
        float o = bnode[t];
        for (int p = 0; p < NP; p++) o += pv[p] * Wnode[p * 2 + t];
        out[b * 2 + t] = o;
    }
}

// ===========================================================================
extern "C" void kernel_launch(void* const* d_in, const int* in_sizes, int n_in,
                              void* d_out, int out_size)
{
    const float* feat  = (const float*)d_in[0];
    const float* Wll   = (const float*)d_in[1];
    const float* bll   = (const float*)d_in[2];
    const float* bn1g  = (const float*)d_in[3];
    const float* bn1b  = (const float*)d_in[4];
    const float* bn1m  = (const float*)d_in[5];
    const float* bn1v  = (const float*)d_in[6];
    const float* Wap   = (const float*)d_in[7];
    const float* bap   = (const float*)d_in[8];
    const float* attw  = (const float*)d_in[9];
    const float* Wpa   = (const float*)d_in[10];
    const float* bpa   = (const float*)d_in[11];
    const float* Wpn   = (const float*)d_in[12];
    const float* bpn   = (const float*)d_in[13];
    const float* bn2g  = (const float*)d_in[14];
    const float* bn2b  = (const float*)d_in[15];
    const float* bn2m  = (const float*)d_in[16];
    const float* bn2v  = (const float*)d_in[17];
    const float* Wpool = (const float*)d_in[18];
    const float* bpool = (const float*)d_in[19];
    const float* Wproj = (const float*)d_in[20];
    const float* bproj = (const float*)d_in[21];
    const float* Wnode = (const float*)d_in[22];
    const float* bnode = (const float*)d_in[23];

    cudaFuncSetAttribute(k1, cudaFuncAttributeMaxDynamicSharedMemorySize, K1_SMEM);
    cudaFuncSetAttribute(k2, cudaFuncAttributeMaxDynamicSharedMemorySize, K2_SMEM);

    k0 <<<(D1 * DSSL + D1 * D2 + NUT + D1 + 255) / 256, 256>>>(
        Wll, Wap, bll, bn1g, bn1b, bn1m, bn1v);
    k1 <<<(MTOT + 125) / 126, 512, K1_SMEM>>>(feat);
    ky <<<NODES / 32, 256>>>(Wpa, Wpn);
    k2 <<<dim3(6, BS), 256, K2_SMEM>>>(bap, attw);
    k2c<<<BS, 256>>>(bpa, bpn, bn2g, bn2b, bn2m, bn2v, Wpool, bpool);
    k4 <<<BS, 128>>>(Wproj, bproj, Wnode, bnode, (float*)d_out);
}

// round 12
// speedup vs baseline: 1.1284x; 1.0498x over previous
#include <cuda_runtime.h>
#include <cuda_bf16.h>
#include <math.h>
#include <stdint.h>

#define BS   256
#define SEQ  201
#define DSSL 1024
#define D1   128
#define D2   64
#define NN   67
#define NP   53
#define NPAIR (NN*NN)      // 4489
#define NU   2278          // upper-triangle pairs (i<=j)
#define NUT  2304
#define EPSBN 1e-5f
#define MTOT  (BS*SEQ)     // 51456
#define NODES (BS*NN)      // 17152

// ---------------- scratch (device globals; no runtime allocation) ----------
__device__ float g_x [NODES * D1];
__device__ float g_y [NODES * D2];         // X @ W_pa
__device__ float g_z [NODES * D2];         // X @ W_pn
__device__ float g_h [NODES * D2];
__device__ float g_sc[NODES];
__device__ float g_logit[BS * NPAIR];
__device__ uint32_t g_pair[NUT];           // packed (i<<8)|j upper-tri table
__device__ float g_sc1[D1], g_of1[D1];     // folded bias+BN1 scale/offset
// pre-swizzled (SW64, 64B rows) pre-split bf16 weight images
__device__ __align__(16) unsigned char g_Bll_h[32 * 8192];
__device__ __align__(16) unsigned char g_Bll_l[32 * 8192];
__device__ __align__(16) unsigned char g_Bap_h[4 * 4096];   // k-slot-permuted
__device__ __align__(16) unsigned char g_Bap_l[4 * 4096];

// ------------------------------ helpers ------------------------------------
__device__ __forceinline__ float selu_f(float v) {
    const float a = 1.6732632423543772f, s = 1.0507009873554805f;
    return v > 0.f ? s * v : s * a * expm1f(v);
}
__device__ __forceinline__ float tanh_f(float x) {
    float e = __expf(2.0f * x);
    return 1.0f - __fdividef(2.0f, e + 1.0f);
}
__host__ __device__ __forceinline__ uint32_t sw64(uint32_t o) {
    return o ^ ((o >> 3) & 0x30);
}
__device__ __forceinline__ uint32_t smem_u32(const void* p) {
    uint32_t a;
    asm("{ .reg .u64 t; cvta.to.shared.u64 t, %1; cvt.u32.u64 %0, t; }"
        : "=r"(a) : "l"(p));
    return a;
}
__device__ __forceinline__ void split2(float v0, float v1, uint32_t& h, uint32_t& l) {
    __nv_bfloat162 hp, lp;
    hp.x = __float2bfloat16(v0);  hp.y = __float2bfloat16(v1);
    lp.x = __float2bfloat16(v0 - __bfloat162float(hp.x));
    lp.y = __float2bfloat16(v1 - __bfloat162float(hp.y));
    h = *reinterpret_cast<uint32_t*>(&hp);
    l = *reinterpret_cast<uint32_t*>(&lp);
}
__device__ __forceinline__ void mma_bf16(float* c,
    uint32_t a0, uint32_t a1, uint32_t a2, uint32_t a3,
    uint32_t b0, uint32_t b1)
{
    asm volatile(
      "mma.sync.aligned.m16n8k16.row.col.f32.bf16.bf16.f32 "
      "{%0,%1,%2,%3},{%4,%5,%6,%7},{%8,%9},{%0,%1,%2,%3};\n"
      : "+f"(c[0]), "+f"(c[1]), "+f"(c[2]), "+f"(c[3])
      : "r"(a0), "r"(a1), "r"(a2), "r"(a3), "r"(b0), "r"(b1));
}
#define LDSM4(r, a) \
    asm volatile("ldmatrix.sync.aligned.m8n8.x4.shared.b16 {%0,%1,%2,%3}, [%4];" \
        : "=r"((r)[0]), "=r"((r)[1]), "=r"((r)[2]), "=r"((r)[3]) : "r"(a))
#define CPA16(d, s) \
    asm volatile("cp.async.ca.shared.global [%0], [%1], 16;" :: "r"(d), "l"(s))
#define CPCOMMIT() asm volatile("cp.async.commit_group;" ::: "memory")
#define CPWAIT()   asm volatile("cp.async.wait_group 0;" ::: "memory")

// ========= K0: weight prep (split+swizzle), pair table, BN1 fold ===========
__global__ void k0(const float* __restrict__ Wll, const float* __restrict__ Wap,
                   const float* __restrict__ bll, const float* __restrict__ g1,
                   const float* __restrict__ b1,  const float* __restrict__ m1,
                   const float* __restrict__ v1)
{
    int idx = blockIdx.x * 256 + threadIdx.x;
    if (idx < D1 * DSSL) {
        int n = idx >> 10, k = idx & 1023;
        float v = Wll[(size_t)k * D1 + n];
        __nv_bfloat16 h = __float2bfloat16(v);
        __nv_bfloat16 l = __float2bfloat16(v - __bfloat162float(h));
        uint32_t dst = (k >> 5) * 8192 + sw64(n * 64 + (k & 31) * 2);
        *(__nv_bfloat16*)(g_Bll_h + dst) = h;
        *(__nv_bfloat16*)(g_Bll_l + dst) = l;
    } else if (idx < D1 * DSSL + D1 * D2) {
        int r = idx - D1 * DSSL;
        int k = r >> 6, c = r & 63;
        float v = Wap[(size_t)k * D2 + c];
        __nv_bfloat16 h = __float2bfloat16(v);
        __nv_bfloat16 l = __float2bfloat16(v - __bfloat162float(h));
        // k-slot permutation: orig kk (within 16) -> mma slot s so that a lane's
        // A elements are Xs[kb + 4*tg .. +3] (contiguous float4).
        int kk = k & 15;
        int s = 2 * (kk >> 2) + (kk & 1) + 8 * ((kk >> 1) & 1);
        uint32_t col = (uint32_t)(((k >> 4) & 1) * 16 + s);
        uint32_t dst = (k >> 5) * 4096 + sw64(c * 64 + col * 2);
        *(__nv_bfloat16*)(g_Bap_h + dst) = h;
        *(__nv_bfloat16*)(g_Bap_l + dst) = l;
    } else if (idx < D1 * DSSL + D1 * D2 + NUT) {
        int u = idx - (D1 * DSSL + D1 * D2);
        if (u < NU) {
            float s = sqrtf((float)((2 * NN + 1) * (2 * NN + 1) - 8 * u));
            int i = (int)(((float)(2 * NN + 1) - s) * 0.5f);
            if (i > NN - 1) i = NN - 1;
            if (i < 0) i = 0;
            while (i > 0 && i * NN - i * (i - 1) / 2 > u) i--;
            while ((i + 1) * NN - (i + 1) * i / 2 <= u) i++;
            int j = i + (u - (i * NN - i * (i - 1) / 2));
            g_pair[u] = (uint32_t)((i << 8) | j);
        } else {
            g_pair[u] = 0xFFFFFFFFu;
        }
    } else if (idx < D1 * DSSL + D1 * D2 + NUT + D1) {
        int c = idx - (D1 * DSSL + D1 * D2 + NUT);
        float sc = rsqrtf(v1[c] + EPSBN) * g1[c];
        g_sc1[c] = sc;
        g_of1[c] = (bll[c] - m1[c]) * sc + b1[c];
    }
}

// ====== K1: feat @ W_ll (hi/lo bf16 3-mma) + fused maxpool3+BN1+selu =======
// 126-row tiles (42 pool groups), BK=32 double-buffered, 16 warps.
#define K1_SMEM 67584
__global__ __launch_bounds__(512) void k1(const float* __restrict__ feat)
{
    extern __shared__ __align__(1024) unsigned char sm1[];
    uint32_t sb = smem_u32(sm1);
    const int t = threadIdx.x, lane = t & 31, wid = t >> 5;
    const int wm = wid >> 1, wn = wid & 1;
    const int m0 = blockIdx.x * 126;

    float acc[8][4];
#pragma unroll
    for (int nf = 0; nf < 8; nf++)
#pragma unroll
        for (int q = 0; q < 4; q++) acc[nf][q] = 0.f;

    const int ar = t >> 2, ak = (t & 3) * 8;
    const int arow_g = min(m0 + ar, MTOT - 1);
    const float* fp = feat + (size_t)arow_g * DSSL + ak;
    float4 fst[2];

    auto ldgA = [&](int kt) {
        const float* p = fp + kt * 32;
        fst[0] = *(const float4*)p;
        fst[1] = *(const float4*)(p + 4);
    };
    auto stsA = [&](int buf) {
        const float* vv = (const float*)fst;
        uint32_t h[4], l[4];
#pragma unroll
        for (int q = 0; q < 4; q++) split2(vv[2 * q], vv[2 * q + 1], h[q], l[q]);
        uint32_t base = (uint32_t)buf * 32768u;
        uint32_t o = sw64(ar * 64 + ak * 2);
        *(uint4*)(sm1 + base + o)        = make_uint4(h[0], h[1], h[2], h[3]);
        *(uint4*)(sm1 + base + 8192 + o) = make_uint4(l[0], l[1], l[2], l[3]);
    };
    auto cpB = [&](int kt, int buf) {
        uint32_t dh = sb + buf * 32768 + 16384 + t * 16;
        uint32_t dl = sb + buf * 32768 + 24576 + t * 16;
        CPA16(dh, g_Bll_h + kt * 8192 + t * 16);
        CPA16(dl, g_Bll_l + kt * 8192 + t * 16);
    };
    auto compute = [&](int buf) {
        uint32_t aH = sb + buf * 32768, aL = aH + 8192;
        uint32_t bH = aH + 16384, bL = aH + 24576;
#pragma unroll
        for (int kf = 0; kf < 2; kf++) {
            uint32_t ah[4], al[4];
            uint32_t off = sw64((wm * 16 + (lane & 15)) * 64 +
                                kf * 32 + (lane >> 4) * 16);
            LDSM4(ah, aH + off);
            LDSM4(al, aL + off);
#pragma unroll
            for (int nf2 = 0; nf2 < 4; nf2++) {
                uint32_t boff = sw64((wn * 64 + nf2 * 16 + (lane & 7) +
                                      ((lane >> 4) & 1) * 8) * 64 +
                                     kf * 32 + ((lane >> 3) & 1) * 16);
                uint32_t bh[4], bl[4];
                LDSM4(bh, bH + boff);
                LDSM4(bl, bL + boff);
                float* c0 = acc[nf2 * 2];
                float* c1 = acc[nf2 * 2 + 1];
                mma_bf16(c0, ah[0], ah[1], ah[2], ah[3], bh[0], bh[1]);
                mma_bf16(c0, ah[0], ah[1], ah[2], ah[3], bl[0], bl[1]);
                mma_bf16(c0, al[0], al[1], al[2], al[3], bh[0], bh[1]);
                mma_bf16(c1, ah[0], ah[1], ah[2], ah[3], bh[2], bh[3]);
                mma_bf16(c1, ah[0], ah[1], ah[2], ah[3], bl[2], bl[3]);
                mma_bf16(c1, al[0], al[1], al[2], al[3], bh[2], bh[3]);
            }
        }
    };

    ldgA(0); cpB(0, 0); CPCOMMIT();
    stsA(0);
    CPWAIT(); __syncthreads();
    for (int kt = 0; kt < 32; kt++) {
        int cur = kt & 1;
        if (kt < 31) { ldgA(kt + 1); cpB(kt + 1, cur ^ 1); CPCOMMIT(); }
        compute(cur);
        if (kt < 31) stsA(cur ^ 1);
        CPWAIT(); __syncthreads();
    }

    // ---- epilogue: stage C in smem, pool 3, folded BN1+selu -> g_x ----
    float* Cep = (float*)sm1;                       // 128 x 132
    const int g = lane >> 2, tg = lane & 3;
#pragma unroll
    for (int nf = 0; nf < 8; nf++) {
        int row = wm * 16 + g;
        int col = wn * 64 + nf * 8 + tg * 2;
        Cep[row * 132 + col]           = acc[nf][0];
        Cep[row * 132 + col + 1]       = acc[nf][1];
        Cep[(row + 8) * 132 + col]     = acc[nf][2];
        Cep[(row + 8) * 132 + col + 1] = acc[nf][3];
    }
    __syncthreads();
#pragma unroll
    for (int pass = 0; pass < 11; pass++) {
        int e = t + pass * 512;
        if (e < 42 * 128) {
            int nl = e >> 7, c = e & 127;
            const float* rp = Cep + (3 * nl) * 132 + c;
            float v = fmaxf(rp[0], fmaxf(rp[132], rp[264]));
            int node = blockIdx.x * 42 + nl;
            if (node < NODES)
                g_x[(size_t)node * D1 + c] = selu_f(v * g_sc1[c] + g_of1[c]);
        }
    }
}

// ====== K2: pair GEMM, warp = 16 pairs x 64 cols, fully sync-free loop =====
// A frags built in registers from Xs (k-slot permutation in B image).
// Each pair-row lives in ONE warp -> epilogue reduces over tg only and
// writes g_logit directly; no partS staging, no barriers in the tile loop.
#define O2_ATT  0
#define O2_BAP  256
#define O2_X    1536
#define O2_WH   37888
#define O2_WL   (O2_WH + 16384)
#define K2_SMEM (O2_WL + 16384)      // 70656
__global__ __launch_bounds__(256, 2) void k2(
    const float* __restrict__ bap, const float* __restrict__ attw)
{
    extern __shared__ __align__(1024) unsigned char sm2[];
    uint32_t sb = smem_u32(sm2);
    float* attS  = (float*)(sm2 + O2_ATT);
    float* bapS  = (float*)(sm2 + O2_BAP);
    float* Xs    = (float*)(sm2 + O2_X);        // 67 x 132
    const int b = blockIdx.y;
    const int t = threadIdx.x, lane = t & 31, w = t >> 5;
    const int g = lane >> 2, tg = lane & 3;

    {   // W hi/lo via cp.async (pre-swizzled, k-slot-permuted image)
        uint32_t dh = sb + O2_WH + t * 64, dl = sb + O2_WL + t * 64;
        const unsigned char* sh = g_Bap_h + t * 64;
        const unsigned char* sl = g_Bap_l + t * 64;
#pragma unroll
        for (int q = 0; q < 4; q++) {
            CPA16(dh + q * 16, sh + q * 16);
            CPA16(dl + q * 16, sl + q * 16);
        }
        CPCOMMIT();
    }
    if (t < 64) { attS[t] = attw[t]; bapS[t] = bap[t]; }
    {   // stage X
        const float* xg = g_x + (size_t)b * NN * D1;
        for (int i = t; i < NN * 32; i += 256) {
            int row = i >> 5, c4 = (i & 31) * 4;
            *(float4*)(Xs + row * 132 + c4) = *(const float4*)(xg + row * D1 + c4);
        }
    }
    CPWAIT(); __syncthreads();

    float* lg = g_logit + (size_t)b * NPAIR;

    for (int tt = 0; tt < 3; tt++) {
        const int u0 = (blockIdx.x * 3 + tt) * 128;
        const int ur0 = u0 + w * 16 + g;           // this lane's row g
        const int ur1 = ur0 + 8;                   // row g+8
        const uint32_t pk0 = g_pair[min(ur0, NU - 1)];
        const uint32_t pk1 = g_pair[min(ur1, NU - 1)];
        const float* xi0 = Xs + (pk0 >> 8) * 132;
        const float* xj0 = Xs + (pk0 & 255) * 132;
        const float* xi1 = Xs + (pk1 >> 8) * 132;
        const float* xj1 = Xs + (pk1 & 255) * 132;

        float acc[8][4];
#pragma unroll
        for (int nf = 0; nf < 8; nf++)
#pragma unroll
            for (int q = 0; q < 4; q++) acc[nf][q] = 0.f;

#pragma unroll
        for (int c16 = 0; c16 < 8; c16++) {
            const int kb = c16 * 16 + 4 * tg;
            float4 vi0 = *(const float4*)(xi0 + kb);
            float4 vj0 = *(const float4*)(xj0 + kb);
            float4 vi1 = *(const float4*)(xi1 + kb);
            float4 vj1 = *(const float4*)(xj1 + kb);
            uint32_t a0h, a0l, a1h, a1l, a2h, a2l, a3h, a3l;
            split2(vi0.x * vj0.x, vi0.y * vj0.y, a0h, a0l);
            split2(vi0.z * vj0.z, vi0.w * vj0.w, a2h, a2l);
            split2(vi1.x * vj1.x, vi1.y * vj1.y, a1h, a1l);
            split2(vi1.z * vj1.z, vi1.w * vj1.w, a3h, a3l);
#pragma unroll
            for (int nf2 = 0; nf2 < 4; nf2++) {
                uint32_t boff = sw64((uint32_t)((nf2 * 16 + (lane & 7) +
                                                 ((lane >> 4) & 1) * 8) * 64 +
                                                (c16 & 1) * 32 + ((lane >> 3) & 1) * 16));
                uint32_t bh[4], bl[4];
                LDSM4(bh, sb + O2_WH + (c16 >> 1) * 4096 + boff);
                LDSM4(bl, sb + O2_WL + (c16 >> 1) * 4096 + boff);
                float* c0 = acc[nf2 * 2];
                float* c1 = acc[nf2 * 2 + 1];
                mma_bf16(c0, a0h, a1h, a2h, a3h, bh[0], bh[1]);
                mma_bf16(c0, a0h, a1h, a2h, a3h, bl[0], bl[1]);
                mma_bf16(c0, a0l, a1l, a2l, a3l, bh[0], bh[1]);
                mma_bf16(c1, a0h, a1h, a2h, a3h, bh[2], bh[3]);
                mma_bf16(c1, a0h, a1h, a2h, a3h, bl[2], bl[3]);
                mma_bf16(c1, a0l, a1l, a2l, a3l, bh[2], bh[3]);
            }
        }

        // epilogue: tanh + dot(att_w); reduce over tg; direct symmetric write
        float p0 = 0.f, p1 = 0.f;
#pragma unroll
        for (int nf = 0; nf < 8; nf++) {
            int col = nf * 8 + tg * 2;
            float w0 = attS[col], w1 = attS[col + 1];
            float q0 = bapS[col], q1 = bapS[col + 1];
            p0 += w0 * tanh_f(acc[nf][0] + q0) + w1 * tanh_f(acc[nf][1] + q1);
            p1 += w0 * tanh_f(acc[nf][2] + q0) + w1 * tanh_f(acc[nf][3] + q1);
        }
        p0 += __shfl_xor_sync(0xffffffffu, p0, 1);
        p0 += __shfl_xor_sync(0xffffffffu, p0, 2);
        p1 += __shfl_xor_sync(0xffffffffu, p1, 1);
        p1 += __shfl_xor_sync(0xffffffffu, p1, 2);
        if (tg == 0) {
            if (ur0 < NU) {
                int i2 = (int)(pk0 >> 8), j2 = (int)(pk0 & 255);
                lg[i2 * NN + j2] = p0;
                lg[j2 * NN + i2] = p0;
            }
            if (ur1 < NU) {
                int i2 = (int)(pk1 >> 8), j2 = (int)(pk1 & 255);
                lg[i2 * NN + j2] = p1;
                lg[j2 * NN + i2] = p1;
            }
        }
    }
}

// ==== KY: Y = x@W_pa, Z = x@W_pn  (raw, no BN) =============================
__global__ __launch_bounds__(256) void ky(
    const float* __restrict__ Wpa, const float* __restrict__ Wpn)
{
    __shared__ float A[32 * 33], Wa[32 * 64], Wb[32 * 64];
    int r0 = blockIdx.x * 32;
    int t  = threadIdx.x;
    int tm = t >> 4, tc = t & 15;
    float accA[2][4] = {}, accB[2][4] = {};

    for (int kt = 0; kt < 4; ++kt) {
#pragma unroll
        for (int s = 0; s < 4; s++) {
            int idx = t + s * 256;
            int m = idx >> 5, k = idx & 31;
            A[m * 33 + k] = g_x[(size_t)(r0 + m) * D1 + kt * 32 + k];
        }
#pragma unroll
        for (int s = 0; s < 8; s++) {
            int idx = t + s * 256;
            int k = idx >> 6, c = idx & 63;
            Wa[k * 64 + c] = Wpa[(size_t)(kt * 32 + k) * D2 + c];
            Wb[k * 64 + c] = Wpn[(size_t)(kt * 32 + k) * D2 + c];
        }
        __syncthreads();
#pragma unroll 8
        for (int k = 0; k < 32; k++) {
            float4 wa = *(const float4*)&Wa[k * 64 + tc * 4];
            float4 wb = *(const float4*)&Wb[k * 64 + tc * 4];
#pragma unroll
            for (int rr = 0; rr < 2; rr++) {
                float a = A[(tm * 2 + rr) * 33 + k];
                accA[rr][0] += a * wa.x;  accB[rr][0] += a * wb.x;
                accA[rr][1] += a * wa.y;  accB[rr][1] += a * wb.y;
                accA[rr][2] += a * wa.z;  accB[rr][2] += a * wb.z;
                accA[rr][3] += a * wa.w;  accB[rr][3] += a * wb.w;
            }
        }
        __syncthreads();
    }

#pragma unroll
    for (int rr = 0; rr < 2; rr++) {
        size_t base = (size_t)(r0 + tm * 2 + rr) * D2 + tc * 4;
        *(float4*)&g_y[base] = make_float4(accA[rr][0], accA[rr][1],
                                           accA[rr][2], accA[rr][3]);
        *(float4*)&g_z[base] = make_float4(accB[rr][0], accB[rr][1],
                                           accB[rr][2], accB[rr][3]);
    }
}

// ==== K2C: softmax + h = selu(BN2(att@Y + Z + biases)) + score =============
__global__ __launch_bounds__(256) void k2c(
    const float* __restrict__ bpa, const float* __restrict__ bpn,
    const float* __restrict__ g2, const float* __restrict__ b2,
    const float* __restrict__ m2, const float* __restrict__ v2,
    const float* __restrict__ Wpool, const float* __restrict__ bpool)
{
    __shared__ float Ys[NN * 68];      // Y staged, stride 68 (16B-aligned rows)
    __shared__ float attS[8][68];
    int b = blockIdx.x, t = threadIdx.x;
    int w = t >> 5, l = t & 31;

    for (int i = t; i < NN * 16; i += 256) {
        int row = i >> 4, q = i & 15;
        *(float4*)(Ys + row * 68 + q * 4) =
            *(const float4*)(g_y + ((size_t)b * NN + row) * D2 + q * 4);
    }
    __syncthreads();

    // per-lane BN2/bias constants for cols c0 = l, c1 = l+32
    const int c0 = l, c1 = l + 32;
    const float bb0 = bpa[c0] + bpn[c0], bb1 = bpa[c1] + bpn[c1];
    const float s0 = rsqrtf(v2[c0] + EPSBN) * g2[c0];
    const float s1 = rsqrtf(v2[c1] + EPSBN) * g2[c1];
    const float m0 = m2[c0], m1v = m2[c1];
    const float o0 = b2[c0], o1 = b2[c1];
    const float wp0 = Wpool[c0], wp1 = Wpool[c1];
    const float bp = bpool[0];

    for (int i = w; i < NN; i += 8) {
        // ---- softmax over j of logit row i ----
        const float* lr = g_logit + (size_t)b * NPAIR + i * NN;
        float v0 = lr[l];
        float v1 = lr[l + 32];
        float vv2 = (l < 3) ? lr[l + 64] : -1e30f;
        float mx = fmaxf(v0, fmaxf(v1, vv2));
#pragma unroll
        for (int o = 16; o > 0; o >>= 1) mx = fmaxf(mx, __shfl_xor_sync(0xffffffffu, mx, o));
        float e0 = __expf(v0 - mx);
        float e1 = __expf(v1 - mx);
        float e2 = (l < 3) ? __expf(vv2 - mx) : 0.f;
        float ss = e0 + e1 + e2;
#pragma unroll
        for (int o = 16; o > 0; o >>= 1) ss += __shfl_xor_sync(0xffffffffu, ss, o);
        float inv = 1.f / ss;
        attS[w][l] = e0 * inv;
        attS[w][l + 32] = e1 * inv;
        if (l < 3) attS[w][l + 64] = e2 * inv;
        __syncwarp();

        // ---- att @ Y: cols c0, c1 ----
        float a0 = 0.f, a1 = 0.f;
        for (int j = 0; j < NN; j++) {
            float a = attS[w][j];
            a0 += a * Ys[j * 68 + c0];
            a1 += a * Ys[j * 68 + c1];
        }
        size_t zb = ((size_t)b * NN + i) * D2;
        float u0 = a0 + g_z[zb + c0] + bb0;
        float u1 = a1 + g_z[zb + c1] + bb1;
        u0 = selu_f((u0 - m0) * s0 + o0);
        u1 = selu_f((u1 - m1v) * s1 + o1);
        g_h[zb + c0] = u0;
        g_h[zb + c1] = u1;
        float sp = u0 * wp0 + u1 * wp1;
#pragma unroll
        for (int o = 16; o > 0; o >>= 1) sp += __shfl_xor_sync(0xffffffffu, sp, o);
        if (l == 0) g_sc[b * NN + i] = 1.f / (1.f + expf(-(sp + bp)));
        __syncwarp();
    }
}

// ======= K4: exact stable top-k(53), gather, proj, 53x2 head ===============
__global__ __launch_bounds__(128) void k4(
    const float* __restrict__ Wproj, const float* __restrict__ bproj,
    const float* __restrict__ Wnode, const float* __restrict__ bnode,
    float* __restrict__ out)
{
    __shared__ float s[NN];
    __shared__ int   sel[NP];
    __shared__ float pv[NP];
    int b = blockIdx.x, t = threadIdx.x;

    if (t < NN) s[t] = g_sc[b * NN + t];
    __syncthreads();
    if (t < NN) {
        float st = s[t]; int rank = 0;
        for (int j = 0; j < NN; j++) {
            float sj = s[j];
            rank += (sj > st) || (sj == st && j < t);
        }
        if (rank < NP) sel[rank] = t;
    }
    __syncthreads();

    int w = t >> 5, lane = t & 31;
    for (int p = w; p < NP; p += 4) {
        int node = sel[p];
        const float* hp = g_h + ((size_t)b * NN + node) * D2;
        float d = hp[lane] * Wproj[lane] + hp[lane + 32] * Wproj[lane + 32];
#pragma unroll
        for (int o = 16; o > 0; o >>= 1) d += __shfl_xor_sync(0xffffffffu, d, o);
        if (lane == 0) pv[p] = s[node] * d + bproj[0];
    }
    __syncthreads();
    if (t < 2) {
        float o = bnode[t];
        for (int p = 0; p < NP; p++) o += pv[p] * Wnode[p * 2 + t];
        out[b * 2 + t] = o;
    }
}

// ===========================================================================
extern "C" void kernel_launch(void* const* d_in, const int* in_sizes, int n_in,
                              void* d_out, int out_size)
{
    const float* feat  = (const float*)d_in[0];
    const float* Wll   = (const float*)d_in[1];
    const float* bll   = (const float*)d_in[2];
    const float* bn1g  = (const float*)d_in[3];
    const float* bn1b  = (const float*)d_in[4];
    const float* bn1m  = (const float*)d_in[5];
    const float* bn1v  = (const float*)d_in[6];
    const float* Wap   = (const float*)d_in[7];
    const float* bap   = (const float*)d_in[8];
    const float* attw  = (const float*)d_in[9];
    const float* Wpa   = (const float*)d_in[10];
    const float* bpa   = (const float*)d_in[11];
    const float* Wpn   = (const float*)d_in[12];
    const float* bpn   = (const float*)d_in[13];
    const float* bn2g  = (const float*)d_in[14];
    const float* bn2b  = (const float*)d_in[15];
    const float* bn2m  = (const float*)d_in[16];
    const float* bn2v  = (const float*)d_in[17];
    const float* Wpool = (const float*)d_in[18];
    const float* bpool = (const float*)d_in[19];
    const float* Wproj = (const float*)d_in[20];
    const float* bproj = (const float*)d_in[21];
    const float* Wnode = (const float*)d_in[22];
    const float* bnode = (const float*)d_in[23];

    cudaFuncSetAttribute(k1, cudaFuncAttributeMaxDynamicSharedMemorySize, K1_SMEM);
    cudaFuncSetAttribute(k2, cudaFuncAttributeMaxDynamicSharedMemorySize, K2_SMEM);

    k0 <<<(D1 * DSSL + D1 * D2 + NUT + D1 + 255) / 256, 256>>>(
        Wll, Wap, bll, bn1g, bn1b, bn1m, bn1v);
    k1 <<<(MTOT + 125) / 126, 512, K1_SMEM>>>(feat);
    ky <<<NODES / 32, 256>>>(Wpa, Wpn);
    k2 <<<dim3(6, BS), 256, K2_SMEM>>>(bap, attw);
    k2c<<<BS, 256>>>(bpa, bpn, bn2g, bn2b, bn2m, bn2v, Wpool, bpool);
    k4 <<<BS, 128>>>(Wproj, bproj, Wnode, bnode, (float*)d_out);
}

// round 13
// speedup vs baseline: 1.1742x; 1.0406x over previous
#include <cuda_runtime.h>
#include <cuda_bf16.h>
#include <math.h>
#include <stdint.h>

#define BS   256
#define SEQ  201
#define DSSL 1024
#define D1   128
#define D2   64
#define NN   67
#define NP   53
#define NPAIR (NN*NN)      // 4489
#define NU   2278          // upper-triangle pairs (i<=j)
#define NUT  2304
#define EPSBN 1e-5f
#define MTOT  (BS*SEQ)     // 51456
#define NODES (BS*NN)      // 17152 = 134*128

// ---------------- scratch (device globals; no runtime allocation) ----------
__device__ float g_x [NODES * D1];
__device__ float g_y [NODES * D2];         // X @ W_pa
__device__ float g_z [NODES * D2];         // X @ W_pn
__device__ float g_h [NODES * D2];
__device__ float g_sc[NODES];
__device__ float g_logit[BS * NPAIR];
__device__ uint32_t g_pair[NUT];           // packed (i<<8)|j upper-tri table
__device__ float g_sc1[D1], g_of1[D1];     // folded bias+BN1 scale/offset
// pre-swizzled (SW64, 64B rows) pre-split bf16 weight images
__device__ __align__(16) unsigned char g_Bll_h[32 * 8192];
__device__ __align__(16) unsigned char g_Bll_l[32 * 8192];
__device__ __align__(16) unsigned char g_Bap_h[4 * 4096];   // k-slot-permuted
__device__ __align__(16) unsigned char g_Bap_l[4 * 4096];
__device__ __align__(16) unsigned char g_Byz_h[4 * 8192];   // [W_pa|W_pn]^T
__device__ __align__(16) unsigned char g_Byz_l[4 * 8192];

// ------------------------------ helpers ------------------------------------
__device__ __forceinline__ float selu_f(float v) {
    const float a = 1.6732632423543772f, s = 1.0507009873554805f;
    return v > 0.f ? s * v : s * a * expm1f(v);
}
__device__ __forceinline__ float tanh_f(float x) {
    float e = __expf(2.0f * x);
    return 1.0f - __fdividef(2.0f, e + 1.0f);
}
__host__ __device__ __forceinline__ uint32_t sw64(uint32_t o) {
    return o ^ ((o >> 3) & 0x30);
}
__device__ __forceinline__ uint32_t smem_u32(const void* p) {
    uint32_t a;
    asm("{ .reg .u64 t; cvta.to.shared.u64 t, %1; cvt.u32.u64 %0, t; }"
        : "=r"(a) : "l"(p));
    return a;
}
__device__ __forceinline__ void split2(float v0, float v1, uint32_t& h, uint32_t& l) {
    __nv_bfloat162 hp, lp;
    hp.x = __float2bfloat16(v0);  hp.y = __float2bfloat16(v1);
    lp.x = __float2bfloat16(v0 - __bfloat162float(hp.x));
    lp.y = __float2bfloat16(v1 - __bfloat162float(hp.y));
    h = *reinterpret_cast<uint32_t*>(&hp);
    l = *reinterpret_cast<uint32_t*>(&lp);
}
__device__ __forceinline__ void mma_bf16(float* c,
    uint32_t a0, uint32_t a1, uint32_t a2, uint32_t a3,
    uint32_t b0, uint32_t b1)
{
    asm volatile(
      "mma.sync.aligned.m16n8k16.row.col.f32.bf16.bf16.f32 "
      "{%0,%1,%2,%3},{%4,%5,%6,%7},{%8,%9},{%0,%1,%2,%3};\n"
      : "+f"(c[0]), "+f"(c[1]), "+f"(c[2]), "+f"(c[3])
      : "r"(a0), "r"(a1), "r"(a2), "r"(a3), "r"(b0), "r"(b1));
}
#define LDSM4(r, a) \
    asm volatile("ldmatrix.sync.aligned.m8n8.x4.shared.b16 {%0,%1,%2,%3}, [%4];" \
        : "=r"((r)[0]), "=r"((r)[1]), "=r"((r)[2]), "=r"((r)[3]) : "r"(a))
#define CPA16(d, s) \
    asm volatile("cp.async.ca.shared.global [%0], [%1], 16;" :: "r"(d), "l"(s))
#define CPCOMMIT() asm volatile("cp.async.commit_group;" ::: "memory")
#define CPWAIT()   asm volatile("cp.async.wait_group 0;" ::: "memory")

// ========= K0: weight prep (split+swizzle), pair table, BN1 fold ===========
#define K0_R1 (D1*DSSL)                 // Wll
#define K0_R2 (K0_R1 + D1*D2)           // Wap
#define K0_R3 (K0_R2 + NUT)             // pair table
#define K0_R4 (K0_R3 + D1)              // BN1 fold
#define K0_R5 (K0_R4 + D1*D1)           // [Wpa|Wpn] image
__global__ void k0(const float* __restrict__ Wll, const float* __restrict__ Wap,
                   const float* __restrict__ bll, const float* __restrict__ g1,
                   const float* __restrict__ b1,  const float* __restrict__ m1,
                   const float* __restrict__ v1,
                   const float* __restrict__ Wpa, const float* __restrict__ Wpn)
{
    int idx = blockIdx.x * 256 + threadIdx.x;
    if (idx < K0_R1) {
        int n = idx >> 10, k = idx & 1023;
        float v = Wll[(size_t)k * D1 + n];
        __nv_bfloat16 h = __float2bfloat16(v);
        __nv_bfloat16 l = __float2bfloat16(v - __bfloat162float(h));
        uint32_t dst = (k >> 5) * 8192 + sw64(n * 64 + (k & 31) * 2);
        *(__nv_bfloat16*)(g_Bll_h + dst) = h;
        *(__nv_bfloat16*)(g_Bll_l + dst) = l;
    } else if (idx < K0_R2) {
        int r = idx - K0_R1;
        int k = r >> 6, c = r & 63;
        float v = Wap[(size_t)k * D2 + c];
        __nv_bfloat16 h = __float2bfloat16(v);
        __nv_bfloat16 l = __float2bfloat16(v - __bfloat162float(h));
        int kk = k & 15;
        int s = 2 * (kk >> 2) + (kk & 1) + 8 * ((kk >> 1) & 1);
        uint32_t col = (uint32_t)(((k >> 4) & 1) * 16 + s);
        uint32_t dst = (k >> 5) * 4096 + sw64(c * 64 + col * 2);
        *(__nv_bfloat16*)(g_Bap_h + dst) = h;
        *(__nv_bfloat16*)(g_Bap_l + dst) = l;
    } else if (idx < K0_R3) {
        int u = idx - K0_R2;
        if (u < NU) {
            float s = sqrtf((float)((2 * NN + 1) * (2 * NN + 1) - 8 * u));
            int i = (int)(((float)(2 * NN + 1) - s) * 0.5f);
            if (i > NN - 1) i = NN - 1;
            if (i < 0) i = 0;
            while (i > 0 && i * NN - i * (i - 1) / 2 > u) i--;
            while ((i + 1) * NN - (i + 1) * i / 2 <= u) i++;
            int j = i + (u - (i * NN - i * (i - 1) / 2));
            g_pair[u] = (uint32_t)((i << 8) | j);
        } else {
            g_pair[u] = 0xFFFFFFFFu;
        }
    } else if (idx < K0_R4) {
        int c = idx - K0_R3;
        float sc = rsqrtf(v1[c] + EPSBN) * g1[c];
        g_sc1[c] = sc;
        g_of1[c] = (bll[c] - m1[c]) * sc + b1[c];
    } else if (idx < K0_R5) {
        int r = idx - K0_R4;                 // [n=0..127][k=0..127]
        int n = r >> 7, k = r & 127;
        float v = (n < 64) ? Wpa[(size_t)k * D2 + n]
                           : Wpn[(size_t)k * D2 + (n - 64)];
        __nv_bfloat16 h = __float2bfloat16(v);
        __nv_bfloat16 l = __float2bfloat16(v - __bfloat162float(h));
        uint32_t dst = (k >> 5) * 8192 + sw64(n * 64 + (k & 31) * 2);
        *(__nv_bfloat16*)(g_Byz_h + dst) = h;
        *(__nv_bfloat16*)(g_Byz_l + dst) = l;
    }
}

// ====== K1: feat @ W_ll (hi/lo bf16 3-mma) + fused maxpool3+BN1+selu =======
#define K1_SMEM 67584
__global__ __launch_bounds__(512) void k1(const float* __restrict__ feat)
{
    extern __shared__ __align__(1024) unsigned char sm1[];
    uint32_t sb = smem_u32(sm1);
    const int t = threadIdx.x, lane = t & 31, wid = t >> 5;
    const int wm = wid >> 1, wn = wid & 1;
    const int m0 = blockIdx.x * 126;

    float acc[8][4];
#pragma unroll
    for (int nf = 0; nf < 8; nf++)
#pragma unroll
        for (int q = 0; q < 4; q++) acc[nf][q] = 0.f;

    const int ar = t >> 2, ak = (t & 3) * 8;
    const int arow_g = min(m0 + ar, MTOT - 1);
    const float* fp = feat + (size_t)arow_g * DSSL + ak;
    float4 fst[2];

    auto ldgA = [&](int kt) {
        const float* p = fp + kt * 32;
        fst[0] = *(const float4*)p;
        fst[1] = *(const float4*)(p + 4);
    };
    auto stsA = [&](int buf) {
        const float* vv = (const float*)fst;
        uint32_t h[4], l[4];
#pragma unroll
        for (int q = 0; q < 4; q++) split2(vv[2 * q], vv[2 * q + 1], h[q], l[q]);
        uint32_t base = (uint32_t)buf * 32768u;
        uint32_t o = sw64(ar * 64 + ak * 2);
        *(uint4*)(sm1 + base + o)        = make_uint4(h[0], h[1], h[2], h[3]);
        *(uint4*)(sm1 + base + 8192 + o) = make_uint4(l[0], l[1], l[2], l[3]);
    };
    auto cpB = [&](int kt, int buf) {
        uint32_t dh = sb + buf * 32768 + 16384 + t * 16;
        uint32_t dl = sb + buf * 32768 + 24576 + t * 16;
        CPA16(dh, g_Bll_h + kt * 8192 + t * 16);
        CPA16(dl, g_Bll_l + kt * 8192 + t * 16);
    };
    auto compute = [&](int buf) {
        uint32_t aH = sb + buf * 32768, aL = aH + 8192;
        uint32_t bH = aH + 16384, bL = aH + 24576;
#pragma unroll
        for (int kf = 0; kf < 2; kf++) {
            uint32_t ah[4], al[4];
            uint32_t off = sw64((wm * 16 + (lane & 15)) * 64 +
                                kf * 32 + (lane >> 4) * 16);
            LDSM4(ah, aH + off);
            LDSM4(al, aL + off);
#pragma unroll
            for (int nf2 = 0; nf2 < 4; nf2++) {
                uint32_t boff = sw64((wn * 64 + nf2 * 16 + (lane & 7) +
                                      ((lane >> 4) & 1) * 8) * 64 +
                                     kf * 32 + ((lane >> 3) & 1) * 16);
                uint32_t bh[4], bl[4];
                LDSM4(bh, bH + boff);
                LDSM4(bl, bL + boff);
                float* c0 = acc[nf2 * 2];
                float* c1 = acc[nf2 * 2 + 1];
                mma_bf16(c0, ah[0], ah[1], ah[2], ah[3], bh[0], bh[1]);
                mma_bf16(c0, ah[0], ah[1], ah[2], ah[3], bl[0], bl[1]);
                mma_bf16(c0, al[0], al[1], al[2], al[3], bh[0], bh[1]);
                mma_bf16(c1, ah[0], ah[1], ah[2], ah[3], bh[2], bh[3]);
                mma_bf16(c1, ah[0], ah[1], ah[2], ah[3], bl[2], bl[3]);
                mma_bf16(c1, al[0], al[1], al[2], al[3], bh[2], bh[3]);
            }
        }
    };

    ldgA(0); cpB(0, 0); CPCOMMIT();
    stsA(0);
    CPWAIT(); __syncthreads();
    for (int kt = 0; kt < 32; kt++) {
        int cur = kt & 1;
        if (kt < 31) { ldgA(kt + 1); cpB(kt + 1, cur ^ 1); CPCOMMIT(); }
        compute(cur);
        if (kt < 31) stsA(cur ^ 1);
        CPWAIT(); __syncthreads();
    }

    float* Cep = (float*)sm1;                       // 128 x 132
    const int g = lane >> 2, tg = lane & 3;
#pragma unroll
    for (int nf = 0; nf < 8; nf++) {
        int row = wm * 16 + g;
        int col = wn * 64 + nf * 8 + tg * 2;
        Cep[row * 132 + col]           = acc[nf][0];
        Cep[row * 132 + col + 1]       = acc[nf][1];
        Cep[(row + 8) * 132 + col]     = acc[nf][2];
        Cep[(row + 8) * 132 + col + 1] = acc[nf][3];
    }
    __syncthreads();
#pragma unroll
    for (int pass = 0; pass < 11; pass++) {
        int e = t + pass * 512;
        if (e < 42 * 128) {
            int nl = e >> 7, c = e & 127;
            const float* rp = Cep + (3 * nl) * 132 + c;
            float v = fmaxf(rp[0], fmaxf(rp[132], rp[264]));
            int node = blockIdx.x * 42 + nl;
            if (node < NODES)
                g_x[(size_t)node * D1 + c] = selu_f(v * g_sc1[c] + g_of1[c]);
        }
    }
}

// ==== KY: [Y|Z] = X @ [W_pa|W_pn]  via hi/lo bf16 3-mma (k1 clone, K=128) ==
#define KY_SMEM 65536
__global__ __launch_bounds__(512) void ky()
{
    extern __shared__ __align__(1024) unsigned char smy[];
    uint32_t sb = smem_u32(smy);
    const int t = threadIdx.x, lane = t & 31, wid = t >> 5;
    const int wm = wid >> 1, wn = wid & 1;
    const int m0 = blockIdx.x * 128;          // NODES = 134*128 exact

    float acc[8][4];
#pragma unroll
    for (int nf = 0; nf < 8; nf++)
#pragma unroll
        for (int q = 0; q < 4; q++) acc[nf][q] = 0.f;

    const int ar = t >> 2, ak = (t & 3) * 8;
    const float* fp = g_x + (size_t)(m0 + ar) * D1 + ak;
    float4 fst[2];

    auto ldgA = [&](int kt) {
        const float* p = fp + kt * 32;
        fst[0] = *(const float4*)p;
        fst[1] = *(const float4*)(p + 4);
    };
    auto stsA = [&](int buf) {
        const float* vv = (const float*)fst;
        uint32_t h[4], l[4];
#pragma unroll
        for (int q = 0; q < 4; q++) split2(vv[2 * q], vv[2 * q + 1], h[q], l[q]);
        uint32_t base = (uint32_t)buf * 32768u;
        uint32_t o = sw64(ar * 64 + ak * 2);
        *(uint4*)(smy + base + o)        = make_uint4(h[0], h[1], h[2], h[3]);
        *(uint4*)(smy + base + 8192 + o) = make_uint4(l[0], l[1], l[2], l[3]);
    };
    auto cpB = [&](int kt, int buf) {
        uint32_t dh = sb + buf * 32768 + 16384 + t * 16;
        uint32_t dl = sb + buf * 32768 + 24576 + t * 16;
        CPA16(dh, g_Byz_h + kt * 8192 + t * 16);
        CPA16(dl, g_Byz_l + kt * 8192 + t * 16);
    };
    auto compute = [&](int buf) {
        uint32_t aH = sb + buf * 32768, aL = aH + 8192;
        uint32_t bH = aH + 16384, bL = aH + 24576;
#pragma unroll
        for (int kf = 0; kf < 2; kf++) {
            uint32_t ah[4], al[4];
            uint32_t off = sw64((wm * 16 + (lane & 15)) * 64 +
                                kf * 32 + (lane >> 4) * 16);
            LDSM4(ah, aH + off);
            LDSM4(al, aL + off);
#pragma unroll
            for (int nf2 = 0; nf2 < 4; nf2++) {
                uint32_t boff = sw64((wn * 64 + nf2 * 16 + (lane & 7) +
                                      ((lane >> 4) & 1) * 8) * 64 +
                                     kf * 32 + ((lane >> 3) & 1) * 16);
                uint32_t bh[4], bl[4];
                LDSM4(bh, bH + boff);
                LDSM4(bl, bL + boff);
                float* c0 = acc[nf2 * 2];
                float* c1 = acc[nf2 * 2 + 1];
                mma_bf16(c0, ah[0], ah[1], ah[2], ah[3], bh[0], bh[1]);
                mma_bf16(c0, ah[0], ah[1], ah[2], ah[3], bl[0], bl[1]);
                mma_bf16(c0, al[0], al[1], al[2], al[3], bh[0], bh[1]);
                mma_bf16(c1, ah[0], ah[1], ah[2], ah[3], bh[2], bh[3]);
                mma_bf16(c1, ah[0], ah[1], ah[2], ah[3], bl[2], bl[3]);
                mma_bf16(c1, al[0], al[1], al[2], al[3], bh[2], bh[3]);
            }
        }
    };

    ldgA(0); cpB(0, 0); CPCOMMIT();
    stsA(0);
    CPWAIT(); __syncthreads();
    for (int kt = 0; kt < 4; kt++) {
        int cur = kt & 1;
        if (kt < 3) { ldgA(kt + 1); cpB(kt + 1, cur ^ 1); CPCOMMIT(); }
        compute(cur);
        if (kt < 3) stsA(cur ^ 1);
        CPWAIT(); __syncthreads();
    }

    // epilogue: wn=0 -> Y, wn=1 -> Z; direct register writes
    const int g = lane >> 2, tg = lane & 3;
    float* dst = wn ? g_z : g_y;
#pragma unroll
    for (int nf = 0; nf < 8; nf++) {
        int row = m0 + wm * 16 + g;
        int col = nf * 8 + tg * 2;
        *(float2*)&dst[(size_t)row * D2 + col] =
            make_float2(acc[nf][0], acc[nf][1]);
        *(float2*)&dst[(size_t)(row + 8) * D2 + col] =
            make_float2(acc[nf][2], acc[nf][3]);
    }
}

// ====== K2: pair GEMM, warp = 16 pairs x 64 cols, fully sync-free loop =====
#define O2_ATT  0
#define O2_BAP  256
#define O2_X    1536
#define O2_WH   37888
#define O2_WL   (O2_WH + 16384)
#define K2_SMEM (O2_WL + 16384)      // 70656
__global__ __launch_bounds__(256, 2) void k2(
    const float* __restrict__ bap, const float* __restrict__ attw)
{
    extern __shared__ __align__(1024) unsigned char sm2[];
    uint32_t sb = smem_u32(sm2);
    float* attS  = (float*)(sm2 + O2_ATT);
    float* bapS  = (float*)(sm2 + O2_BAP);
    float* Xs    = (float*)(sm2 + O2_X);        // 67 x 132
    const int b = blockIdx.y;
    const int t = threadIdx.x, lane = t & 31, w = t >> 5;
    const int g = lane >> 2, tg = lane & 3;

    {
        uint32_t dh = sb + O2_WH + t * 64, dl = sb + O2_WL + t * 64;
        const unsigned char* sh = g_Bap_h + t * 64;
        const unsigned char* sl = g_Bap_l + t * 64;
#pragma unroll
        for (int q = 0; q < 4; q++) {
            CPA16(dh + q * 16, sh + q * 16);
            CPA16(dl + q * 16, sl + q * 16);
        }
        CPCOMMIT();
    }
    if (t < 64) { attS[t] = attw[t]; bapS[t] = bap[t]; }
    {
        const float* xg = g_x + (size_t)b * NN * D1;
        for (int i = t; i < NN * 32; i += 256) {
            int row = i >> 5, c4 = (i & 31) * 4;
            *(float4*)(Xs + row * 132 + c4) = *(const float4*)(xg + row * D1 + c4);
        }
    }
    CPWAIT(); __syncthreads();

    float* lg = g_logit + (size_t)b * NPAIR;

    for (int tt = 0; tt < 3; tt++) {
        const int u0 = (blockIdx.x * 3 + tt) * 128;
        const int ur0 = u0 + w * 16 + g;
        const int ur1 = ur0 + 8;
        const uint32_t pk0 = g_pair[min(ur0, NU - 1)];
        const uint32_t pk1 = g_pair[min(ur1, NU - 1)];
        const float* xi0 = Xs + (pk0 >> 8) * 132;
        const float* xj0 = Xs + (pk0 & 255) * 132;
        const float* xi1 = Xs + (pk1 >> 8) * 132;
        const float* xj1 = Xs + (pk1 & 255) * 132;

        float acc[8][4];
#pragma unroll
        for (int nf = 0; nf < 8; nf++)
#pragma unroll
            for (int q = 0; q < 4; q++) acc[nf][q] = 0.f;

#pragma unroll
        for (int c16 = 0; c16 < 8; c16++) {
            const int kb = c16 * 16 + 4 * tg;
            float4 vi0 = *(const float4*)(xi0 + kb);
            float4 vj0 = *(const float4*)(xj0 + kb);
            float4 vi1 = *(const float4*)(xi1 + kb);
            float4 vj1 = *(const float4*)(xj1 + kb);
            uint32_t a0h, a0l, a1h, a1l, a2h, a2l, a3h, a3l;
            split2(vi0.x * vj0.x, vi0.y * vj0.y, a0h, a0l);
            split2(vi0.z * vj0.z, vi0.w * vj0.w, a2h, a2l);
            split2(vi1.x * vj1.x, vi1.y * vj1.y, a1h, a1l);
            split2(vi1.z * vj1.z, vi1.w * vj1.w, a3h, a3l);
#pragma unroll
            for (int nf2 = 0; nf2 < 4; nf2++) {
                uint32_t boff = sw64((uint32_t)((nf2 * 16 + (lane & 7) +
                                                 ((lane >> 4) & 1) * 8) * 64 +
                                                (c16 & 1) * 32 + ((lane >> 3) & 1) * 16));
                uint32_t bh[4], bl[4];
                LDSM4(bh, sb + O2_WH + (c16 >> 1) * 4096 + boff);
                LDSM4(bl, sb + O2_WL + (c16 >> 1) * 4096 + boff);
                float* c0 = acc[nf2 * 2];
                float* c1 = acc[nf2 * 2 + 1];
                mma_bf16(c0, a0h, a1h, a2h, a3h, bh[0], bh[1]);
                mma_bf16(c0, a0h, a1h, a2h, a3h, bl[0], bl[1]);
                mma_bf16(c0, a0l, a1l, a2l, a3l, bh[0], bh[1]);
                mma_bf16(c1, a0h, a1h, a2h, a3h, bh[2], bh[3]);
                mma_bf16(c1, a0h, a1h, a2h, a3h, bl[2], bl[3]);
                mma_bf16(c1, a0l, a1l, a2l, a3l, bh[2], bh[3]);
            }
        }

        float p0 = 0.f, p1 = 0.f;
#pragma unroll
        for (int nf = 0; nf < 8; nf++) {
            int col = nf * 8 + tg * 2;
            float w0 = attS[col], w1 = attS[col + 1];
            float q0 = bapS[col], q1 = bapS[col + 1];
            p0 += w0 * tanh_f(acc[nf][0] + q0) + w1 * tanh_f(acc[nf][1] + q1);
            p1 += w0 * tanh_f(acc[nf][2] + q0) + w1 * tanh_f(acc[nf][3] + q1);
        }
        p0 += __shfl_xor_sync(0xffffffffu, p0, 1);
        p0 += __shfl_xor_sync(0xffffffffu, p0, 2);
        p1 += __shfl_xor_sync(0xffffffffu, p1, 1);
        p1 += __shfl_xor_sync(0xffffffffu, p1, 2);
        if (tg == 0) {
            if (ur0 < NU) {
                int i2 = (int)(pk0 >> 8), j2 = (int)(pk0 & 255);
                lg[i2 * NN + j2] = p0;
                lg[j2 * NN + i2] = p0;
            }
            if (ur1 < NU) {
                int i2 = (int)(pk1 >> 8), j2 = (int)(pk1 & 255);
                lg[i2 * NN + j2] = p1;
                lg[j2 * NN + i2] = p1;
            }
        }
    }
}

// ==== K2C: softmax + h = selu(BN2(att@Y + Z + biases)) + score =============
__global__ __launch_bounds__(256) void k2c(
    const float* __restrict__ bpa, const float* __restrict__ bpn,
    const float* __restrict__ g2, const float* __restrict__ b2,
    const float* __restrict__ m2, const float* __restrict__ v2,
    const float* __restrict__ Wpool, const float* __restrict__ bpool)
{
    __shared__ float Ys[NN * 68];
    __shared__ float attS[8][68];
    int b = blockIdx.x, t = threadIdx.x;
    int w = t >> 5, l = t & 31;

    for (int i = t; i < NN * 16; i += 256) {
        int row = i >> 4, q = i & 15;
        *(float4*)(Ys + row * 68 + q * 4) =
            *(const float4*)(g_y + ((size_t)b * NN + row) * D2 + q * 4);
    }
    __syncthreads();

    const int c0 = l, c1 = l + 32;
    const float bb0 = bpa[c0] + bpn[c0], bb1 = bpa[c1] + bpn[c1];
    const float s0 = rsqrtf(v2[c0] + EPSBN) * g2[c0];
    const float s1 = rsqrtf(v2[c1] + EPSBN) * g2[c1];
    const float m0 = m2[c0], m1v = m2[c1];
    const float o0 = b2[c0], o1 = b2[c1];
    const float wp0 = Wpool[c0], wp1 = Wpool[c1];
    const float bp = bpool[0];

    for (int i = w; i < NN; i += 8) {
        const float* lr = g_logit + (size_t)b * NPAIR + i * NN;
        float v0 = lr[l];
        float v1 = lr[l + 32];
        float vv2 = (l < 3) ? lr[l + 64] : -1e30f;
        float mx = fmaxf(v0, fmaxf(v1, vv2));
#pragma unroll
        for (int o = 16; o > 0; o >>= 1) mx = fmaxf(mx, __shfl_xor_sync(0xffffffffu, mx, o));
        float e0 = __expf(v0 - mx);
        float e1 = __expf(v1 - mx);
        float e2 = (l < 3) ? __expf(vv2 - mx) : 0.f;
        float ss = e0 + e1 + e2;
#pragma unroll
        for (int o = 16; o > 0; o >>= 1) ss += __shfl_xor_sync(0xffffffffu, ss, o);
        float inv = 1.f / ss;
        attS[w][l] = e0 * inv;
        attS[w][l + 32] = e1 * inv;
        if (l < 3) attS[w][l + 64] = e2 * inv;
        __syncwarp();

        float a0 = 0.f, a1 = 0.f;
        for (int j = 0; j < NN; j++) {
            float a = attS[w][j];
            a0 += a * Ys[j * 68 + c0];
            a1 += a * Ys[j * 68 + c1];
        }
        size_t zb = ((size_t)b * NN + i) * D2;
        float u0 = a0 + g_z[zb + c0] + bb0;
        float u1 = a1 + g_z[zb + c1] + bb1;
        u0 = selu_f((u0 - m0) * s0 + o0);
        u1 = selu_f((u1 - m1v) * s1 + o1);
        g_h[zb + c0] = u0;
        g_h[zb + c1] = u1;
        float sp = u0 * wp0 + u1 * wp1;
#pragma unroll
        for (int o = 16; o > 0; o >>= 1) sp += __shfl_xor_sync(0xffffffffu, sp, o);
        if (l == 0) g_sc[b * NN + i] = 1.f / (1.f + expf(-(sp + bp)));
        __syncwarp();
    }
}

// ======= K4: exact stable top-k(53), gather, proj, 53x2 head ===============
__global__ __launch_bounds__(128) void k4(
    const float* __restrict__ Wproj, const float* __restrict__ bproj,
    const float* __restrict__ Wnode, const float* __restrict__ bnode,
    float* __restrict__ out)
{
    __shared__ float s[NN];
    __shared__ int   sel[NP];
    __shared__ float pv[NP];
    int b = blockIdx.x, t = threadIdx.x;

    if (t < NN) s[t] = g_sc[b * NN + t];
    __syncthreads();
    if (t < NN) {
        float st = s[t]; int rank = 0;
        for (int j = 0; j < NN; j++) {
            float sj = s[j];
            rank += (sj > st) || (sj == st && j < t);
        }
        if (rank < NP) sel[rank] = t;
    }
    __syncthreads();

    int w = t >> 5, lane = t & 31;
    for (int p = w; p < NP; p += 4) {
        int node = sel[p];
        const float* hp = g_h + ((size_t)b * NN + node) * D2;
        float d = hp[lane] * Wproj[lane] + hp[lane + 32] * Wproj[lane + 32];
#pragma unroll
        for (int o = 16; o > 0; o >>= 1) d += __shfl_xor_sync(0xffffffffu, d, o);
        if (lane == 0) pv[p] = s[node] * d + bproj[0];
    }
    __syncthreads();
    if (t < 2) {
        float o = bnode[t];
        for (int p = 0; p < NP; p++) o += pv[p] * Wnode[p * 2 + t];
        out[b * 2 + t] = o;
    }
}

// ===========================================================================
extern "C" void kernel_launch(void* const* d_in, const int* in_sizes, int n_in,
                              void* d_out, int out_size)
{
    const float* feat  = (const float*)d_in[0];
    const float* Wll   = (const float*)d_in[1];
    const float* bll   = (const float*)d_in[2];
    const float* bn1g  = (const float*)d_in[3];
    const float* bn1b  = (const float*)d_in[4];
    const float* bn1m  = (const float*)d_in[5];
    const float* bn1v  = (const float*)d_in[6];
    const float* Wap   = (const float*)d_in[7];
    const float* bap   = (const float*)d_in[8];
    const float* attw  = (const float*)d_in[9];
    const float* Wpa   = (const float*)d_in[10];
    const float* bpa   = (const float*)d_in[11];
    const float* Wpn   = (const float*)d_in[12];
    const float* bpn   = (const float*)d_in[13];
    const float* bn2g  = (const float*)d_in[14];
    const float* bn2b  = (const float*)d_in[15];
    const float* bn2m  = (const float*)d_in[16];
    const float* bn2v  = (const float*)d_in[17];
    const float* Wpool = (const float*)d_in[18];
    const float* bpool = (const float*)d_in[19];
    const float* Wproj = (const float*)d_in[20];
    const float* bproj = (const float*)d_in[21];
    const float* Wnode = (const float*)d_in[22];
    const float* bnode = (const float*)d_in[23];

    cudaFuncSetAttribute(k1, cudaFuncAttributeMaxDynamicSharedMemorySize, K1_SMEM);
    cudaFuncSetAttribute(ky, cudaFuncAttributeMaxDynamicSharedMemorySize, KY_SMEM);
    cudaFuncSetAttribute(k2, cudaFuncAttributeMaxDynamicSharedMemorySize, K2_SMEM);

    k0 <<<(K0_R5 + 255) / 256, 256>>>(Wll, Wap, bll, bn1g, bn1b, bn1m, bn1v,
                                      Wpa, Wpn);
    k1 <<<(MTOT + 125) / 126, 512, K1_SMEM>>>(feat);
    ky <<<NODES / 128, 512, KY_SMEM>>>();
    k2 <<<dim3(6, BS), 256, K2_SMEM>>>(bap, attw);
    k2c<<<BS, 256>>>(bpa, bpn, bn2g, bn2b, bn2m, bn2v, Wpool, bpool);
    k4 <<<BS, 128>>>(Wproj, bproj, Wnode, bnode, (float*)d_out);
}